// round 3
// baseline (speedup 1.0000x reference)
#include <cuda_runtime.h>
#include <math.h>
#include <stdint.h>

#define SEQ    1024
#define DIM    1024
#define NH     16
#define HD     64
#define LAYERS 6
#define BATCH  2
#define ROWS   (BATCH*SEQ)   // 2048
#define FFD    (4*DIM)       // 4096
#define VOCAB  32000

// ---- scratch (device globals: allocation-free) ----
__device__ float g_x  [ROWS*DIM];
__device__ float g_qkv[ROWS*3*DIM];
__device__ float g_ao [ROWS*DIM];
__device__ float g_ff [ROWS*FFD];
__device__ float g_t  [ROWS*DIM];

// =================== embedding ===================
__global__ void embed_kernel(const int* __restrict__ X, const float* __restrict__ tok,
                             const float* __restrict__ pos, float* __restrict__ x) {
    int row = blockIdx.x;
    int s   = row % SEQ;
    int v   = X[row];
    const float* te = tok + (size_t)v * DIM;
    const float* pe = pos + (size_t)s * DIM;
    float* xr = x + (size_t)row * DIM;
    for (int d = threadIdx.x; d < DIM; d += blockDim.x)
        xr[d] = te[d] + pe[d];
}

// =================== tf32 tensor-core GEMM (fragment-layout A, 2-stage smem) ===================
// C[M,N] = A[M,K] @ B[K,N] + bias, optional exact-GELU epilogue.
// BM=128, BN=128, BK=16. 256 threads = 8 warps (2x4). Warp tile 64x32.
__device__ __forceinline__ float gelu_exact(float v) {
    return 0.5f * v * (1.0f + erff(v * 0.70710678118654752f));
}
__device__ __forceinline__ uint32_t tf32cvt(float f) {
    uint32_t u; asm("cvt.rna.tf32.f32 %0, %1;" : "=r"(u) : "f"(f)); return u;
}

// SMEM layout (uint32):
//   Af: [2 stage][2 ks][8 mtile][32 lane][4 reg]   (frag-order A)  stage stride 2048
//   Bf: [2 stage][16 k][132 n]                                     stage stride 2112
#define AF_STAGE 2048
#define BF_STAGE 2112
#define GEMM_SMEM ((2*AF_STAGE + 2*BF_STAGE) * 4)   // 33280 bytes

__device__ __forceinline__ void storeA_frag(uint32_t* Af, int stage, int m, int kA, float4 v) {
    // lane' = (m&7) | ((k&3)<<3);  reg = ((m>>3)&1) | (((kA>>2)&1)<<1);  k = kA+j
    int ks  = kA >> 3;
    int reg = ((m >> 3) & 1) | (((kA >> 2) & 1) << 1);
    uint32_t* p = Af + stage*AF_STAGE + ks*1024 + (m >> 4)*128 + (m & 7)*4 + reg;
    p[0]  = tf32cvt(v.x);
    p[32] = tf32cvt(v.y);
    p[64] = tf32cvt(v.z);
    p[96] = tf32cvt(v.w);
}

template<int EPI>
__global__ __launch_bounds__(256, 2) void gemm_tc(
    const float* __restrict__ A, const float* __restrict__ B,
    const float* __restrict__ bias, float* __restrict__ C,
    int N, int K) {
    extern __shared__ uint32_t smem_u[];
    uint32_t* Af = smem_u;
    uint32_t* Bf = smem_u + 2*AF_STAGE;

    const int t    = threadIdx.x;
    const int warp = t >> 5, lane = t & 31;
    const int wm   = warp >> 2, wn = warp & 3;      // 2 x 4 warp grid
    const int g    = lane >> 2, tig = lane & 3;
    const int bm   = blockIdx.y * 128;
    const int bn   = blockIdx.x * 128;

    const float* Abase = A + (size_t)bm * K;
    const float* Bbase = B + bn;

    // global-load geometry
    const int rA = t >> 2, kA = (t & 3) << 2;       // A rows rA, rA+64; k cols kA..kA+3
    const int rB = t >> 5, cB = (t & 31) << 2;      // B rows rB, rB+8;  n cols cB..cB+3

    // reader lane offset into Af (floats): lane' * 4
    const int laneoff = ((lane >> 2) | ((lane & 3) << 3)) * 4;

    float acc[4][4][4];
    #pragma unroll
    for (int i = 0; i < 4; i++)
        #pragma unroll
        for (int j = 0; j < 4; j++)
            #pragma unroll
            for (int r = 0; r < 4; r++) acc[i][j][r] = 0.f;

    float4 ra0, ra1, rb0, rb1;

    #define LDG_TILE(k0) do {                                                    \
        ra0 = *(const float4*)(Abase + (size_t)rA        * K + (k0) + kA);       \
        ra1 = *(const float4*)(Abase + (size_t)(rA + 64) * K + (k0) + kA);       \
        rb0 = *(const float4*)(Bbase + (size_t)((k0) + rB)     * N + cB);        \
        rb1 = *(const float4*)(Bbase + (size_t)((k0) + rB + 8) * N + cB);        \
    } while (0)

    #define STS_TILE(stg) do {                                                   \
        storeA_frag(Af, (stg), rA,      kA, ra0);                                \
        storeA_frag(Af, (stg), rA + 64, kA, ra1);                                \
        uint32_t* bp0 = Bf + (stg)*BF_STAGE + rB*132 + cB;                        \
        uint32_t* bp1 = Bf + (stg)*BF_STAGE + (rB + 8)*132 + cB;                  \
        uint4 w;                                                                  \
        w.x=tf32cvt(rb0.x); w.y=tf32cvt(rb0.y); w.z=tf32cvt(rb0.z); w.w=tf32cvt(rb0.w); \
        *(uint4*)bp0 = w;                                                         \
        w.x=tf32cvt(rb1.x); w.y=tf32cvt(rb1.y); w.z=tf32cvt(rb1.z); w.w=tf32cvt(rb1.w); \
        *(uint4*)bp1 = w;                                                         \
    } while (0)

    LDG_TILE(0);
    STS_TILE(0);
    __syncthreads();

    const int nkt = K >> 4;
    for (int kt = 0; kt < nkt; kt++) {
        const int cur = kt & 1;
        if (kt + 1 < nkt) LDG_TILE((kt + 1) << 4);

        #pragma unroll
        for (int ks = 0; ks < 2; ks++) {
            const uint32_t* ab = Af + cur*AF_STAGE + ks*1024 + laneoff;
            uint4 af4[4];
            #pragma unroll
            for (int mt = 0; mt < 4; mt++)
                af4[mt] = *(const uint4*)(ab + (wm*4 + mt)*128);
            const uint32_t* bb = Bf + cur*BF_STAGE + (ks*8 + tig)*132 + wn*32 + g;
            #pragma unroll
            for (int nt = 0; nt < 4; nt++) {
                uint32_t b0 = bb[nt*8];
                uint32_t b1 = bb[nt*8 + 4*132];
                #pragma unroll
                for (int mt = 0; mt < 4; mt++) {
                    asm volatile(
                        "mma.sync.aligned.m16n8k8.row.col.f32.tf32.tf32.f32 "
                        "{%0,%1,%2,%3}, {%4,%5,%6,%7}, {%8,%9}, {%0,%1,%2,%3};\n"
                        : "+f"(acc[mt][nt][0]), "+f"(acc[mt][nt][1]),
                          "+f"(acc[mt][nt][2]), "+f"(acc[mt][nt][3])
                        : "r"(af4[mt].x), "r"(af4[mt].y), "r"(af4[mt].z), "r"(af4[mt].w),
                          "r"(b0), "r"(b1));
                }
            }
        }
        if (kt + 1 < nkt) {
            STS_TILE((kt + 1) & 1);
            __syncthreads();
        }
    }
    #undef LDG_TILE
    #undef STS_TILE

    // epilogue
    #pragma unroll
    for (int nt = 0; nt < 4; nt++) {
        int n = bn + wn * 32 + nt * 8 + 2 * tig;
        float2 bv = *(const float2*)(bias + n);
        #pragma unroll
        for (int mt = 0; mt < 4; mt++) {
            int r = bm + wm * 64 + mt * 16 + g;
            float2 o0 = make_float2(acc[mt][nt][0] + bv.x, acc[mt][nt][1] + bv.y);
            float2 o1 = make_float2(acc[mt][nt][2] + bv.x, acc[mt][nt][3] + bv.y);
            if (EPI == 1) {
                o0.x = gelu_exact(o0.x); o0.y = gelu_exact(o0.y);
                o1.x = gelu_exact(o1.x); o1.y = gelu_exact(o1.y);
            }
            *(float2*)(C + (size_t)r * N + n)       = o0;
            *(float2*)(C + (size_t)(r + 8) * N + n) = o1;
        }
    }
}

// =================== fused causal attention (flash-style, fp32) ===================
#define ATTN_SMEM (4*64*65*4)

__global__ __launch_bounds__(256) void attn_kernel(const float* __restrict__ qkv,
                                                   float* __restrict__ out) {
    extern __shared__ float sm[];
    float (*Qs)[65] = (float(*)[65])(sm);
    float (*Ks)[65] = (float(*)[65])(sm + 64*65);
    float (*Vs)[65] = (float(*)[65])(sm + 2*64*65);
    float (*Ps)[65] = (float(*)[65])(sm + 3*64*65);
    const int qt = blockIdx.x, h = blockIdx.y, b = blockIdx.z;
    const int t  = threadIdx.x;
    const int qi = t >> 2, g = t & 3;

    const int RS = 3*DIM;
    const float* qbase = qkv + (size_t)(b*SEQ) * RS + h * (3*HD);

    #pragma unroll
    for (int i = 0; i < 4; i++) {
        int f = t + i*256;
        int r = f >> 4;
        int c = (f & 15) << 2;
        float4 v = *(const float4*)(qbase + (size_t)(qt*64 + r) * RS + c);
        Qs[r][c]=v.x; Qs[r][c+1]=v.y; Qs[r][c+2]=v.z; Qs[r][c+3]=v.w;
    }

    float m = -INFINITY, l = 0.f;
    float o[16];
    #pragma unroll
    for (int i = 0; i < 16; i++) o[i] = 0.f;
    const int qg = qt*64 + qi;

    for (int kt = 0; kt <= qt; kt++) {
        __syncthreads();
        #pragma unroll
        for (int i = 0; i < 4; i++) {
            int f = t + i*256;
            int r = f >> 4;
            int c = (f & 15) << 2;
            const float* base = qbase + (size_t)(kt*64 + r) * RS + 64 + c;
            float4 kv = *(const float4*)(base);
            Ks[r][c]=kv.x; Ks[r][c+1]=kv.y; Ks[r][c+2]=kv.z; Ks[r][c+3]=kv.w;
            float4 vv = *(const float4*)(base + 64);
            Vs[r][c]=vv.x; Vs[r][c+1]=vv.y; Vs[r][c+2]=vv.z; Vs[r][c+3]=vv.w;
        }
        __syncthreads();

        float sreg[16];
        #pragma unroll
        for (int j = 0; j < 16; j++) sreg[j] = 0.f;
        #pragma unroll
        for (int d0 = 0; d0 < 64; d0 += 16) {
            float q[16];
            #pragma unroll
            for (int dd = 0; dd < 16; dd++) q[dd] = Qs[qi][d0+dd];
            #pragma unroll
            for (int j = 0; j < 16; j++) {
                const float* kr = &Ks[j*4 + g][d0];
                #pragma unroll
                for (int dd = 0; dd < 16; dd++) sreg[j] += q[dd] * kr[dd];
            }
        }
        float tmax = -INFINITY;
        #pragma unroll
        for (int j = 0; j < 16; j++) {
            int kgl = kt*64 + j*4 + g;
            float sv = sreg[j] * 0.125f;
            if (kgl > qg) sv = -INFINITY;
            sreg[j] = sv;
            tmax = fmaxf(tmax, sv);
        }
        tmax = fmaxf(tmax, __shfl_xor_sync(0xffffffffu, tmax, 1));
        tmax = fmaxf(tmax, __shfl_xor_sync(0xffffffffu, tmax, 2));
        float nm   = fmaxf(m, tmax);
        float corr = expf(m - nm);
        m = nm;

        float lsum = 0.f;
        #pragma unroll
        for (int j = 0; j < 16; j++) {
            float p = expf(sreg[j] - m);
            lsum += p;
            Ps[qi][j*4 + g] = p;
        }
        lsum += __shfl_xor_sync(0xffffffffu, lsum, 1);
        lsum += __shfl_xor_sync(0xffffffffu, lsum, 2);
        l = l * corr + lsum;
        #pragma unroll
        for (int c = 0; c < 16; c++) o[c] *= corr;
        __syncwarp();

        for (int kj = 0; kj < 64; kj++) {
            float p = Ps[qi][kj];
            const float* vr = &Vs[kj][0];
            #pragma unroll
            for (int c = 0; c < 16; c++)
                o[c] += p * vr[c*4 + g];
        }
    }

    float inv = 1.f / l;
    float* orow = out + (size_t)(b*SEQ + qg) * DIM + h * HD;
    #pragma unroll
    for (int c = 0; c < 16; c++)
        orow[c*4 + g] = o[c] * inv;
}

// =================== residual add + LayerNorm ===================
__global__ __launch_bounds__(256) void add_ln_kernel(
    const float* __restrict__ x, const float* __restrict__ a,
    const float* __restrict__ scale, const float* __restrict__ bias,
    float* __restrict__ out, int has_a) {
    int row = blockIdx.x;
    const float* xr = x + (size_t)row * DIM;
    const float* ar = a + (size_t)row * DIM;
    int t = threadIdx.x;
    float v[4];
    float s = 0.f, s2 = 0.f;
    #pragma unroll
    for (int i = 0; i < 4; i++) {
        int d = t + i*256;
        float val = xr[d] + (has_a ? ar[d] : 0.f);
        v[i] = val; s += val; s2 += val*val;
    }
    __shared__ float red[2][8];
    #pragma unroll
    for (int off = 16; off; off >>= 1) {
        s  += __shfl_xor_sync(0xffffffffu, s,  off);
        s2 += __shfl_xor_sync(0xffffffffu, s2, off);
    }
    if ((t & 31) == 0) { red[0][t>>5] = s; red[1][t>>5] = s2; }
    __syncthreads();
    float ts = 0.f, ts2 = 0.f;
    #pragma unroll
    for (int i = 0; i < 8; i++) { ts += red[0][i]; ts2 += red[1][i]; }
    float mean = ts * (1.0f/DIM);
    float var  = ts2 * (1.0f/DIM) - mean*mean;
    float inv  = rsqrtf(var + 1e-5f);
    float* orow = out + (size_t)row * DIM;
    #pragma unroll
    for (int i = 0; i < 4; i++) {
        int d = t + i*256;
        orow[d] = (v[i] - mean) * inv * scale[d] + bias[d];
    }
}

// =================== final row softmax over VOCAB (in place) ===================
__global__ __launch_bounds__(256) void softmax_kernel(float* __restrict__ out) {
    int row = blockIdx.x;
    float* r = out + (size_t)row * VOCAB;
    int t = threadIdx.x;
    float mx = -INFINITY;
    for (int i = t; i < VOCAB; i += 256) mx = fmaxf(mx, r[i]);
    __shared__ float redm[8], reds[8];
    #pragma unroll
    for (int off = 16; off; off >>= 1) mx = fmaxf(mx, __shfl_xor_sync(0xffffffffu, mx, off));
    if ((t & 31) == 0) redm[t>>5] = mx;
    __syncthreads();
    float bm = -INFINITY;
    #pragma unroll
    for (int i = 0; i < 8; i++) bm = fmaxf(bm, redm[i]);
    float sum = 0.f;
    for (int i = t; i < VOCAB; i += 256) {
        float e = expf(r[i] - bm);
        r[i] = e; sum += e;
    }
    #pragma unroll
    for (int off = 16; off; off >>= 1) sum += __shfl_xor_sync(0xffffffffu, sum, off);
    if ((t & 31) == 0) reds[t>>5] = sum;
    __syncthreads();
    float bs = 0.f;
    #pragma unroll
    for (int i = 0; i < 8; i++) bs += reds[i];
    float inv = 1.f / bs;
    for (int i = t; i < VOCAB; i += 256) r[i] *= inv;
}

// =================== launch ===================
extern "C" void kernel_launch(void* const* d_in, const int* in_sizes, int n_in,
                              void* d_out, int out_size) {
    const int*   X      = (const int*)  d_in[0];
    const float* tok    = (const float*)d_in[1];
    const float* pos    = (const float*)d_in[2];
    const float* qkv_w  = (const float*)d_in[3];
    const float* qkv_b  = (const float*)d_in[4];
    const float* out_w  = (const float*)d_in[5];
    const float* out_b  = (const float*)d_in[6];
    const float* ln1_s  = (const float*)d_in[7];
    const float* ln1_b  = (const float*)d_in[8];
    const float* ln2_s  = (const float*)d_in[9];
    const float* ln2_b  = (const float*)d_in[10];
    const float* ff1_w  = (const float*)d_in[11];
    const float* ff1_b  = (const float*)d_in[12];
    const float* ff2_w  = (const float*)d_in[13];
    const float* ff2_b  = (const float*)d_in[14];
    const float* lnf_s  = (const float*)d_in[15];
    const float* lnf_b  = (const float*)d_in[16];
    const float* head_w = (const float*)d_in[17];
    const float* head_b = (const float*)d_in[18];
    float* outp = (float*)d_out;

    float *x, *qkvb, *ao, *ff, *tmp;
    cudaGetSymbolAddress((void**)&x,    g_x);
    cudaGetSymbolAddress((void**)&qkvb, g_qkv);
    cudaGetSymbolAddress((void**)&ao,   g_ao);
    cudaGetSymbolAddress((void**)&ff,   g_ff);
    cudaGetSymbolAddress((void**)&tmp,  g_t);

    cudaFuncSetAttribute(attn_kernel, cudaFuncAttributeMaxDynamicSharedMemorySize, ATTN_SMEM);

    embed_kernel<<<ROWS, 256>>>(X, tok, pos, x);

    for (int l = 0; l < LAYERS; l++) {
        gemm_tc<0><<<dim3(3*DIM/128, ROWS/128), 256, GEMM_SMEM>>>(x, qkv_w, qkv_b, qkvb, 3*DIM, DIM);
        attn_kernel<<<dim3(SEQ/64, NH, BATCH), 256, ATTN_SMEM>>>(qkvb, ao);
        gemm_tc<0><<<dim3(DIM/128, ROWS/128), 256, GEMM_SMEM>>>(ao, out_w, out_b, tmp, DIM, DIM);
        add_ln_kernel<<<ROWS, 256>>>(x, tmp, ln1_s, ln1_b, x, 1);
        gemm_tc<1><<<dim3(FFD/128, ROWS/128), 256, GEMM_SMEM>>>(x, ff1_w, ff1_b, ff, FFD, DIM);
        gemm_tc<0><<<dim3(DIM/128, ROWS/128), 256, GEMM_SMEM>>>(ff, ff2_w, ff2_b, tmp, DIM, FFD);
        add_ln_kernel<<<ROWS, 256>>>(x, tmp, ln2_s, ln2_b, x, 1);
    }
    add_ln_kernel<<<ROWS, 256>>>(x, x, lnf_s, lnf_b, x, 0);
    gemm_tc<0><<<dim3(VOCAB/128, ROWS/128), 256, GEMM_SMEM>>>(x, head_w, head_b, outp, VOCAB, DIM);
    softmax_kernel<<<ROWS, 256>>>(outp);
}

// round 4
// speedup vs baseline: 1.4336x; 1.4336x over previous
#include <cuda_runtime.h>
#include <cuda_fp16.h>
#include <math.h>
#include <stdint.h>

#define SEQ    1024
#define DIM    1024
#define NH     16
#define HD     64
#define LAYERS 6
#define BATCH  2
#define ROWS   (BATCH*SEQ)   // 2048
#define FFD    (4*DIM)       // 4096
#define VOCAB  32000

// ---- scratch (device globals: allocation-free) ----
__device__ float g_x  [ROWS*DIM];
__device__ float g_qkv[ROWS*3*DIM];
__device__ float g_ao [ROWS*DIM];
__device__ float g_ff [ROWS*FFD];
__device__ float g_t  [ROWS*DIM];

// =================== embedding ===================
__global__ void embed_kernel(const int* __restrict__ X, const float* __restrict__ tok,
                             const float* __restrict__ pos, float* __restrict__ x) {
    int row = blockIdx.x;
    int s   = row % SEQ;
    int v   = X[row];
    const float* te = tok + (size_t)v * DIM;
    const float* pe = pos + (size_t)s * DIM;
    float* xr = x + (size_t)row * DIM;
    for (int d = threadIdx.x; d < DIM; d += blockDim.x)
        xr[d] = te[d] + pe[d];
}

// =================== fp16 tensor-core GEMM (fp32 accumulate) ===================
// C[M,N] = A[M,K] @ B[K,N] + bias, optional exact-GELU epilogue.
// BM=128, BN=128, BK=16. 256 threads = 8 warps (2x4). Warp tile 64x32.
// mma.sync.aligned.m16n8k16.row.col.f32.f16.f16.f32
__device__ __forceinline__ float gelu_exact(float v) {
    return 0.5f * v * (1.0f + erff(v * 0.70710678118654752f));
}
__device__ __forceinline__ uint32_t packh2(float a, float b) {
    __half2 h = __floats2half2_rn(a, b);
    return *(uint32_t*)&h;
}

template<int EPI>
__global__ __launch_bounds__(256, 2) void gemm_tc(
    const float* __restrict__ A, const float* __restrict__ B,
    const float* __restrict__ bias, float* __restrict__ C,
    int N, int K) {
    // As2[m][kk]: half2 over k-pairs, row stride 12 (8 used) -> conflict-free reads
    // Bs2[kk][n]: half2(B[2kk][n],B[2kk+1][n]), row stride 136 -> conflict-free reads
    __shared__ uint32_t As2[128][12];
    __shared__ uint32_t Bs2[8][136];

    const int t    = threadIdx.x;
    const int warp = t >> 5, lane = t & 31;
    const int wm   = warp >> 2, wn = warp & 3;      // 2 x 4 warp grid
    const int g    = lane >> 2, tig = lane & 3;
    const int bm   = blockIdx.y * 128;
    const int bn   = blockIdx.x * 128;

    const float* Abase = A + (size_t)bm * K;
    const float* Bbase = B + bn;

    // global-load geometry
    const int rA = t >> 2, kA = (t & 3) << 2;       // A rows rA, rA+64; k cols kA..kA+3
    const int rB = t >> 5, cB = (t & 31) << 2;      // B k-pair rB (rows 2rB,2rB+1); n cols cB..cB+3

    float acc[4][4][4];
    #pragma unroll
    for (int i = 0; i < 4; i++)
        #pragma unroll
        for (int j = 0; j < 4; j++)
            #pragma unroll
            for (int r = 0; r < 4; r++) acc[i][j][r] = 0.f;

    float4 ra0, ra1, rb0, rb1;

    #define LDG_TILE(k0) do {                                                    \
        ra0 = *(const float4*)(Abase + (size_t)rA        * K + (k0) + kA);       \
        ra1 = *(const float4*)(Abase + (size_t)(rA + 64) * K + (k0) + kA);       \
        rb0 = *(const float4*)(Bbase + (size_t)((k0) + 2*rB    ) * N + cB);      \
        rb1 = *(const float4*)(Bbase + (size_t)((k0) + 2*rB + 1) * N + cB);      \
    } while (0)

    #define STS_TILE() do {                                                      \
        uint2 wa;                                                                 \
        wa.x = packh2(ra0.x, ra0.y); wa.y = packh2(ra0.z, ra0.w);                 \
        *(uint2*)&As2[rA][kA >> 1] = wa;                                          \
        wa.x = packh2(ra1.x, ra1.y); wa.y = packh2(ra1.z, ra1.w);                 \
        *(uint2*)&As2[rA + 64][kA >> 1] = wa;                                     \
        uint4 wb;                                                                 \
        wb.x = packh2(rb0.x, rb1.x); wb.y = packh2(rb0.y, rb1.y);                 \
        wb.z = packh2(rb0.z, rb1.z); wb.w = packh2(rb0.w, rb1.w);                 \
        *(uint4*)&Bs2[rB][cB] = wb;                                               \
    } while (0)

    LDG_TILE(0);
    STS_TILE();
    __syncthreads();

    const int nkt = K >> 4;
    for (int kt = 0; kt < nkt; kt++) {
        if (kt + 1 < nkt) LDG_TILE((kt + 1) << 4);

        // a fragments: a0=As2[m][tig], a1=As2[m+8][tig], a2=As2[m][tig+4], a3=As2[m+8][tig+4]
        uint32_t a[4][4];
        #pragma unroll
        for (int mt = 0; mt < 4; mt++) {
            int m = wm * 64 + mt * 16 + g;
            a[mt][0] = As2[m    ][tig];
            a[mt][1] = As2[m + 8][tig];
            a[mt][2] = As2[m    ][tig + 4];
            a[mt][3] = As2[m + 8][tig + 4];
        }
        #pragma unroll
        for (int nt = 0; nt < 4; nt++) {
            int n = wn * 32 + nt * 8 + g;
            uint32_t b0 = Bs2[tig    ][n];
            uint32_t b1 = Bs2[tig + 4][n];
            #pragma unroll
            for (int mt = 0; mt < 4; mt++) {
                asm volatile(
                    "mma.sync.aligned.m16n8k16.row.col.f32.f16.f16.f32 "
                    "{%0,%1,%2,%3}, {%4,%5,%6,%7}, {%8,%9}, {%0,%1,%2,%3};\n"
                    : "+f"(acc[mt][nt][0]), "+f"(acc[mt][nt][1]),
                      "+f"(acc[mt][nt][2]), "+f"(acc[mt][nt][3])
                    : "r"(a[mt][0]), "r"(a[mt][1]), "r"(a[mt][2]), "r"(a[mt][3]),
                      "r"(b0), "r"(b1));
            }
        }
        __syncthreads();
        if (kt + 1 < nkt) {
            STS_TILE();
            __syncthreads();
        }
    }
    #undef LDG_TILE
    #undef STS_TILE

    // epilogue: c0/c1 at (row g, cols 2tig,2tig+1), c2/c3 at row g+8
    #pragma unroll
    for (int nt = 0; nt < 4; nt++) {
        int n = bn + wn * 32 + nt * 8 + 2 * tig;
        float2 bv = *(const float2*)(bias + n);
        #pragma unroll
        for (int mt = 0; mt < 4; mt++) {
            int r = bm + wm * 64 + mt * 16 + g;
            float2 o0 = make_float2(acc[mt][nt][0] + bv.x, acc[mt][nt][1] + bv.y);
            float2 o1 = make_float2(acc[mt][nt][2] + bv.x, acc[mt][nt][3] + bv.y);
            if (EPI == 1) {
                o0.x = gelu_exact(o0.x); o0.y = gelu_exact(o0.y);
                o1.x = gelu_exact(o1.x); o1.y = gelu_exact(o1.y);
            }
            *(float2*)(C + (size_t)r * N + n)       = o0;
            *(float2*)(C + (size_t)(r + 8) * N + n) = o1;
        }
    }
}

// =================== fused causal attention (flash-style, fp32) ===================
#define ATTN_SMEM (4*64*65*4)

__global__ __launch_bounds__(256) void attn_kernel(const float* __restrict__ qkv,
                                                   float* __restrict__ out) {
    extern __shared__ float sm[];
    float (*Qs)[65] = (float(*)[65])(sm);
    float (*Ks)[65] = (float(*)[65])(sm + 64*65);
    float (*Vs)[65] = (float(*)[65])(sm + 2*64*65);
    float (*Ps)[65] = (float(*)[65])(sm + 3*64*65);
    const int qt = blockIdx.x, h = blockIdx.y, b = blockIdx.z;
    const int t  = threadIdx.x;
    const int qi = t >> 2, g = t & 3;

    const int RS = 3*DIM;
    const float* qbase = qkv + (size_t)(b*SEQ) * RS + h * (3*HD);

    #pragma unroll
    for (int i = 0; i < 4; i++) {
        int f = t + i*256;
        int r = f >> 4;
        int c = (f & 15) << 2;
        float4 v = *(const float4*)(qbase + (size_t)(qt*64 + r) * RS + c);
        Qs[r][c]=v.x; Qs[r][c+1]=v.y; Qs[r][c+2]=v.z; Qs[r][c+3]=v.w;
    }

    float m = -INFINITY, l = 0.f;
    float o[16];
    #pragma unroll
    for (int i = 0; i < 16; i++) o[i] = 0.f;
    const int qg = qt*64 + qi;

    for (int kt = 0; kt <= qt; kt++) {
        __syncthreads();
        #pragma unroll
        for (int i = 0; i < 4; i++) {
            int f = t + i*256;
            int r = f >> 4;
            int c = (f & 15) << 2;
            const float* base = qbase + (size_t)(kt*64 + r) * RS + 64 + c;
            float4 kv = *(const float4*)(base);
            Ks[r][c]=kv.x; Ks[r][c+1]=kv.y; Ks[r][c+2]=kv.z; Ks[r][c+3]=kv.w;
            float4 vv = *(const float4*)(base + 64);
            Vs[r][c]=vv.x; Vs[r][c+1]=vv.y; Vs[r][c+2]=vv.z; Vs[r][c+3]=vv.w;
        }
        __syncthreads();

        float sreg[16];
        #pragma unroll
        for (int j = 0; j < 16; j++) sreg[j] = 0.f;
        #pragma unroll
        for (int d0 = 0; d0 < 64; d0 += 16) {
            float q[16];
            #pragma unroll
            for (int dd = 0; dd < 16; dd++) q[dd] = Qs[qi][d0+dd];
            #pragma unroll
            for (int j = 0; j < 16; j++) {
                const float* kr = &Ks[j*4 + g][d0];
                #pragma unroll
                for (int dd = 0; dd < 16; dd++) sreg[j] += q[dd] * kr[dd];
            }
        }
        float tmax = -INFINITY;
        #pragma unroll
        for (int j = 0; j < 16; j++) {
            int kgl = kt*64 + j*4 + g;
            float sv = sreg[j] * 0.125f;
            if (kgl > qg) sv = -INFINITY;
            sreg[j] = sv;
            tmax = fmaxf(tmax, sv);
        }
        tmax = fmaxf(tmax, __shfl_xor_sync(0xffffffffu, tmax, 1));
        tmax = fmaxf(tmax, __shfl_xor_sync(0xffffffffu, tmax, 2));
        float nm   = fmaxf(m, tmax);
        float corr = expf(m - nm);
        m = nm;

        float lsum = 0.f;
        #pragma unroll
        for (int j = 0; j < 16; j++) {
            float p = expf(sreg[j] - m);
            lsum += p;
            Ps[qi][j*4 + g] = p;
        }
        lsum += __shfl_xor_sync(0xffffffffu, lsum, 1);
        lsum += __shfl_xor_sync(0xffffffffu, lsum, 2);
        l = l * corr + lsum;
        #pragma unroll
        for (int c = 0; c < 16; c++) o[c] *= corr;
        __syncwarp();

        for (int kj = 0; kj < 64; kj++) {
            float p = Ps[qi][kj];
            const float* vr = &Vs[kj][0];
            #pragma unroll
            for (int c = 0; c < 16; c++)
                o[c] += p * vr[c*4 + g];
        }
    }

    float inv = 1.f / l;
    float* orow = out + (size_t)(b*SEQ + qg) * DIM + h * HD;
    #pragma unroll
    for (int c = 0; c < 16; c++)
        orow[c*4 + g] = o[c] * inv;
}

// =================== residual add + LayerNorm ===================
__global__ __launch_bounds__(256) void add_ln_kernel(
    const float* __restrict__ x, const float* __restrict__ a,
    const float* __restrict__ scale, const float* __restrict__ bias,
    float* __restrict__ out, int has_a) {
    int row = blockIdx.x;
    const float* xr = x + (size_t)row * DIM;
    const float* ar = a + (size_t)row * DIM;
    int t = threadIdx.x;
    float v[4];
    float s = 0.f, s2 = 0.f;
    #pragma unroll
    for (int i = 0; i < 4; i++) {
        int d = t + i*256;
        float val = xr[d] + (has_a ? ar[d] : 0.f);
        v[i] = val; s += val; s2 += val*val;
    }
    __shared__ float red[2][8];
    #pragma unroll
    for (int off = 16; off; off >>= 1) {
        s  += __shfl_xor_sync(0xffffffffu, s,  off);
        s2 += __shfl_xor_sync(0xffffffffu, s2, off);
    }
    if ((t & 31) == 0) { red[0][t>>5] = s; red[1][t>>5] = s2; }
    __syncthreads();
    float ts = 0.f, ts2 = 0.f;
    #pragma unroll
    for (int i = 0; i < 8; i++) { ts += red[0][i]; ts2 += red[1][i]; }
    float mean = ts * (1.0f/DIM);
    float var  = ts2 * (1.0f/DIM) - mean*mean;
    float inv  = rsqrtf(var + 1e-5f);
    float* orow = out + (size_t)row * DIM;
    #pragma unroll
    for (int i = 0; i < 4; i++) {
        int d = t + i*256;
        orow[d] = (v[i] - mean) * inv * scale[d] + bias[d];
    }
}

// =================== final row softmax over VOCAB (in place) ===================
__global__ __launch_bounds__(256) void softmax_kernel(float* __restrict__ out) {
    int row = blockIdx.x;
    float* r = out + (size_t)row * VOCAB;
    int t = threadIdx.x;
    float mx = -INFINITY;
    for (int i = t; i < VOCAB; i += 256) mx = fmaxf(mx, r[i]);
    __shared__ float redm[8], reds[8];
    #pragma unroll
    for (int off = 16; off; off >>= 1) mx = fmaxf(mx, __shfl_xor_sync(0xffffffffu, mx, off));
    if ((t & 31) == 0) redm[t>>5] = mx;
    __syncthreads();
    float bm = -INFINITY;
    #pragma unroll
    for (int i = 0; i < 8; i++) bm = fmaxf(bm, redm[i]);
    float sum = 0.f;
    for (int i = t; i < VOCAB; i += 256) {
        float e = expf(r[i] - bm);
        r[i] = e; sum += e;
    }
    #pragma unroll
    for (int off = 16; off; off >>= 1) sum += __shfl_xor_sync(0xffffffffu, sum, off);
    if ((t & 31) == 0) reds[t>>5] = sum;
    __syncthreads();
    float bs = 0.f;
    #pragma unroll
    for (int i = 0; i < 8; i++) bs += reds[i];
    float inv = 1.f / bs;
    for (int i = t; i < VOCAB; i += 256) r[i] *= inv;
}

// =================== launch ===================
extern "C" void kernel_launch(void* const* d_in, const int* in_sizes, int n_in,
                              void* d_out, int out_size) {
    const int*   X      = (const int*)  d_in[0];
    const float* tok    = (const float*)d_in[1];
    const float* pos    = (const float*)d_in[2];
    const float* qkv_w  = (const float*)d_in[3];
    const float* qkv_b  = (const float*)d_in[4];
    const float* out_w  = (const float*)d_in[5];
    const float* out_b  = (const float*)d_in[6];
    const float* ln1_s  = (const float*)d_in[7];
    const float* ln1_b  = (const float*)d_in[8];
    const float* ln2_s  = (const float*)d_in[9];
    const float* ln2_b  = (const float*)d_in[10];
    const float* ff1_w  = (const float*)d_in[11];
    const float* ff1_b  = (const float*)d_in[12];
    const float* ff2_w  = (const float*)d_in[13];
    const float* ff2_b  = (const float*)d_in[14];
    const float* lnf_s  = (const float*)d_in[15];
    const float* lnf_b  = (const float*)d_in[16];
    const float* head_w = (const float*)d_in[17];
    const float* head_b = (const float*)d_in[18];
    float* outp = (float*)d_out;

    float *x, *qkvb, *ao, *ff, *tmp;
    cudaGetSymbolAddress((void**)&x,    g_x);
    cudaGetSymbolAddress((void**)&qkvb, g_qkv);
    cudaGetSymbolAddress((void**)&ao,   g_ao);
    cudaGetSymbolAddress((void**)&ff,   g_ff);
    cudaGetSymbolAddress((void**)&tmp,  g_t);

    cudaFuncSetAttribute(attn_kernel, cudaFuncAttributeMaxDynamicSharedMemorySize, ATTN_SMEM);

    embed_kernel<<<ROWS, 256>>>(X, tok, pos, x);

    for (int l = 0; l < LAYERS; l++) {
        gemm_tc<0><<<dim3(3*DIM/128, ROWS/128), 256>>>(x, qkv_w, qkv_b, qkvb, 3*DIM, DIM);
        attn_kernel<<<dim3(SEQ/64, NH, BATCH), 256, ATTN_SMEM>>>(qkvb, ao);
        gemm_tc<0><<<dim3(DIM/128, ROWS/128), 256>>>(ao, out_w, out_b, tmp, DIM, DIM);
        add_ln_kernel<<<ROWS, 256>>>(x, tmp, ln1_s, ln1_b, x, 1);
        gemm_tc<1><<<dim3(FFD/128, ROWS/128), 256>>>(x, ff1_w, ff1_b, ff, FFD, DIM);
        gemm_tc<0><<<dim3(DIM/128, ROWS/128), 256>>>(ff, ff2_w, ff2_b, tmp, DIM, FFD);
        add_ln_kernel<<<ROWS, 256>>>(x, tmp, ln2_s, ln2_b, x, 1);
    }
    add_ln_kernel<<<ROWS, 256>>>(x, x, lnf_s, lnf_b, x, 0);
    gemm_tc<0><<<dim3(VOCAB/128, ROWS/128), 256>>>(x, head_w, head_b, outp, VOCAB, DIM);
    softmax_kernel<<<ROWS, 256>>>(outp);
}

// round 5
// speedup vs baseline: 1.5201x; 1.0604x over previous
#include <cuda_runtime.h>
#include <cuda_fp16.h>
#include <math.h>
#include <stdint.h>

#define SEQ    1024
#define DIM    1024
#define NH     16
#define HD     64
#define LAYERS 6
#define BATCH  2
#define ROWS   (BATCH*SEQ)   // 2048
#define FFD    (4*DIM)       // 4096
#define VOCAB  32000

// ---- scratch (device globals: allocation-free) ----
__device__ float g_x  [ROWS*DIM];
__device__ float g_qkv[ROWS*3*DIM];
__device__ float g_ao [ROWS*DIM];
__device__ float g_ff [ROWS*FFD];
__device__ float g_t  [ROWS*DIM];

// =================== embedding ===================
__global__ void embed_kernel(const int* __restrict__ X, const float* __restrict__ tok,
                             const float* __restrict__ pos, float* __restrict__ x) {
    int row = blockIdx.x;
    int s   = row % SEQ;
    int v   = X[row];
    const float* te = tok + (size_t)v * DIM;
    const float* pe = pos + (size_t)s * DIM;
    float* xr = x + (size_t)row * DIM;
    for (int d = threadIdx.x; d < DIM; d += blockDim.x)
        xr[d] = te[d] + pe[d];
}

// =================== fp16 tensor-core GEMM (fp32 accumulate, 2-stage smem) ===================
// C[M,N] = A[M,K] @ B[K,N] + bias, optional exact-GELU epilogue.
// MT = m-tiles (16 rows) per warp: MT=4 -> BM=128, MT=2 -> BM=64. BN=128, BK=16.
// 256 threads = 8 warps (2x4). mma.sync.aligned.m16n8k16.row.col.f32.f16.f16.f32
__device__ __forceinline__ float gelu_exact(float v) {
    return 0.5f * v * (1.0f + erff(v * 0.70710678118654752f));
}
__device__ __forceinline__ uint32_t packh2(float a, float b) {
    __half2 h = __floats2half2_rn(a, b);
    return *(uint32_t*)&h;
}

template<int EPI, int MT>
__global__ __launch_bounds__(256, 2) void gemm_tc(
    const float* __restrict__ A, const float* __restrict__ B,
    const float* __restrict__ bias, float* __restrict__ C,
    int N, int K) {
    constexpr int BM = MT * 32;
    // As2[m][kk]: half2 over k-pairs, row stride 12 (8 used) -> conflict-free reads
    // Bs2[kk][n]: half2(B[2kk][n],B[2kk+1][n]), row stride 136 -> conflict-free reads
    __shared__ uint32_t As2[2][BM][12];
    __shared__ uint32_t Bs2[2][8][136];

    const int t    = threadIdx.x;
    const int warp = t >> 5, lane = t & 31;
    const int wm   = warp >> 2, wn = warp & 3;      // 2 x 4 warp grid
    const int g    = lane >> 2, tig = lane & 3;
    const int bm   = blockIdx.y * BM;
    const int bn   = blockIdx.x * 128;

    const float* Abase = A + (size_t)bm * K;
    const float* Bbase = B + bn;

    // global-load geometry
    const int rA = t >> 2, kA = (t & 3) << 2;       // A rows rA (+64 if BM=128); k cols kA..kA+3
    const int rB = t >> 5, cB = (t & 31) << 2;      // B k-pair rB; n cols cB..cB+3

    float acc[MT][4][4];
    #pragma unroll
    for (int i = 0; i < MT; i++)
        #pragma unroll
        for (int j = 0; j < 4; j++)
            #pragma unroll
            for (int r = 0; r < 4; r++) acc[i][j][r] = 0.f;

    float4 ra0, ra1, rb0, rb1;

    #define LDG_TILE(k0) do {                                                    \
        ra0 = *(const float4*)(Abase + (size_t)rA        * K + (k0) + kA);       \
        if (MT == 4)                                                              \
            ra1 = *(const float4*)(Abase + (size_t)(rA + 64) * K + (k0) + kA);   \
        rb0 = *(const float4*)(Bbase + (size_t)((k0) + 2*rB    ) * N + cB);      \
        rb1 = *(const float4*)(Bbase + (size_t)((k0) + 2*rB + 1) * N + cB);      \
    } while (0)

    #define STS_TILE(stg) do {                                                   \
        uint2 wa;                                                                 \
        wa.x = packh2(ra0.x, ra0.y); wa.y = packh2(ra0.z, ra0.w);                 \
        *(uint2*)&As2[stg][rA][kA >> 1] = wa;                                     \
        if (MT == 4) {                                                            \
            wa.x = packh2(ra1.x, ra1.y); wa.y = packh2(ra1.z, ra1.w);             \
            *(uint2*)&As2[stg][rA + 64][kA >> 1] = wa;                            \
        }                                                                         \
        uint4 wb;                                                                 \
        wb.x = packh2(rb0.x, rb1.x); wb.y = packh2(rb0.y, rb1.y);                 \
        wb.z = packh2(rb0.z, rb1.z); wb.w = packh2(rb0.w, rb1.w);                 \
        *(uint4*)&Bs2[stg][rB][cB] = wb;                                          \
    } while (0)

    LDG_TILE(0);
    STS_TILE(0);
    __syncthreads();

    const int nkt = K >> 4;
    for (int kt = 0; kt < nkt; kt++) {
        const int cur = kt & 1;
        if (kt + 1 < nkt) LDG_TILE((kt + 1) << 4);   // in-flight during MMAs

        uint32_t a[MT][4];
        #pragma unroll
        for (int mt = 0; mt < MT; mt++) {
            int m = wm * (MT * 16) + mt * 16 + g;
            a[mt][0] = As2[cur][m    ][tig];
            a[mt][1] = As2[cur][m + 8][tig];
            a[mt][2] = As2[cur][m    ][tig + 4];
            a[mt][3] = As2[cur][m + 8][tig + 4];
        }
        #pragma unroll
        for (int nt = 0; nt < 4; nt++) {
            int n = wn * 32 + nt * 8 + g;
            uint32_t b0 = Bs2[cur][tig    ][n];
            uint32_t b1 = Bs2[cur][tig + 4][n];
            #pragma unroll
            for (int mt = 0; mt < MT; mt++) {
                asm volatile(
                    "mma.sync.aligned.m16n8k16.row.col.f32.f16.f16.f32 "
                    "{%0,%1,%2,%3}, {%4,%5,%6,%7}, {%8,%9}, {%0,%1,%2,%3};\n"
                    : "+f"(acc[mt][nt][0]), "+f"(acc[mt][nt][1]),
                      "+f"(acc[mt][nt][2]), "+f"(acc[mt][nt][3])
                    : "r"(a[mt][0]), "r"(a[mt][1]), "r"(a[mt][2]), "r"(a[mt][3]),
                      "r"(b0), "r"(b1));
            }
        }
        if (kt + 1 < nkt) STS_TILE(cur ^ 1);   // other stage: no pre-barrier needed
        __syncthreads();
    }
    #undef LDG_TILE
    #undef STS_TILE

    // epilogue: c0/c1 at (row g, cols 2tig,2tig+1), c2/c3 at row g+8
    #pragma unroll
    for (int nt = 0; nt < 4; nt++) {
        int n = bn + wn * 32 + nt * 8 + 2 * tig;
        float2 bv = *(const float2*)(bias + n);
        #pragma unroll
        for (int mt = 0; mt < MT; mt++) {
            int r = bm + wm * (MT * 16) + mt * 16 + g;
            float2 o0 = make_float2(acc[mt][nt][0] + bv.x, acc[mt][nt][1] + bv.y);
            float2 o1 = make_float2(acc[mt][nt][2] + bv.x, acc[mt][nt][3] + bv.y);
            if (EPI == 1) {
                o0.x = gelu_exact(o0.x); o0.y = gelu_exact(o0.y);
                o1.x = gelu_exact(o1.x); o1.y = gelu_exact(o1.y);
            }
            *(float2*)(C + (size_t)r * N + n)       = o0;
            *(float2*)(C + (size_t)(r + 8) * N + n) = o1;
        }
    }
}

// =================== fused causal attention (flash-style, fp32) ===================
#define ATTN_SMEM (4*64*65*4)

__global__ __launch_bounds__(256) void attn_kernel(const float* __restrict__ qkv,
                                                   float* __restrict__ out) {
    extern __shared__ float sm[];
    float (*Qs)[65] = (float(*)[65])(sm);
    float (*Ks)[65] = (float(*)[65])(sm + 64*65);
    float (*Vs)[65] = (float(*)[65])(sm + 2*64*65);
    float (*Ps)[65] = (float(*)[65])(sm + 3*64*65);
    const int qt = blockIdx.x, h = blockIdx.y, b = blockIdx.z;
    const int t  = threadIdx.x;
    const int qi = t >> 2, g = t & 3;

    const int RS = 3*DIM;
    const float* qbase = qkv + (size_t)(b*SEQ) * RS + h * (3*HD);

    #pragma unroll
    for (int i = 0; i < 4; i++) {
        int f = t + i*256;
        int r = f >> 4;
        int c = (f & 15) << 2;
        float4 v = *(const float4*)(qbase + (size_t)(qt*64 + r) * RS + c);
        Qs[r][c]=v.x; Qs[r][c+1]=v.y; Qs[r][c+2]=v.z; Qs[r][c+3]=v.w;
    }

    float m = -INFINITY, l = 0.f;
    float o[16];
    #pragma unroll
    for (int i = 0; i < 16; i++) o[i] = 0.f;
    const int qg = qt*64 + qi;

    for (int kt = 0; kt <= qt; kt++) {
        __syncthreads();
        #pragma unroll
        for (int i = 0; i < 4; i++) {
            int f = t + i*256;
            int r = f >> 4;
            int c = (f & 15) << 2;
            const float* base = qbase + (size_t)(kt*64 + r) * RS + 64 + c;
            float4 kv = *(const float4*)(base);
            Ks[r][c]=kv.x; Ks[r][c+1]=kv.y; Ks[r][c+2]=kv.z; Ks[r][c+3]=kv.w;
            float4 vv = *(const float4*)(base + 64);
            Vs[r][c]=vv.x; Vs[r][c+1]=vv.y; Vs[r][c+2]=vv.z; Vs[r][c+3]=vv.w;
        }
        __syncthreads();

        float sreg[16];
        #pragma unroll
        for (int j = 0; j < 16; j++) sreg[j] = 0.f;
        #pragma unroll
        for (int d0 = 0; d0 < 64; d0 += 16) {
            float q[16];
            #pragma unroll
            for (int dd = 0; dd < 16; dd++) q[dd] = Qs[qi][d0+dd];
            #pragma unroll
            for (int j = 0; j < 16; j++) {
                const float* kr = &Ks[j*4 + g][d0];
                #pragma unroll
                for (int dd = 0; dd < 16; dd++) sreg[j] += q[dd] * kr[dd];
            }
        }
        float tmax = -INFINITY;
        #pragma unroll
        for (int j = 0; j < 16; j++) {
            int kgl = kt*64 + j*4 + g;
            float sv = sreg[j] * 0.125f;
            if (kgl > qg) sv = -INFINITY;
            sreg[j] = sv;
            tmax = fmaxf(tmax, sv);
        }
        tmax = fmaxf(tmax, __shfl_xor_sync(0xffffffffu, tmax, 1));
        tmax = fmaxf(tmax, __shfl_xor_sync(0xffffffffu, tmax, 2));
        float nm   = fmaxf(m, tmax);
        float corr = expf(m - nm);
        m = nm;

        float lsum = 0.f;
        #pragma unroll
        for (int j = 0; j < 16; j++) {
            float p = expf(sreg[j] - m);
            lsum += p;
            Ps[qi][j*4 + g] = p;
        }
        lsum += __shfl_xor_sync(0xffffffffu, lsum, 1);
        lsum += __shfl_xor_sync(0xffffffffu, lsum, 2);
        l = l * corr + lsum;
        #pragma unroll
        for (int c = 0; c < 16; c++) o[c] *= corr;
        __syncwarp();

        for (int kj = 0; kj < 64; kj++) {
            float p = Ps[qi][kj];
            const float* vr = &Vs[kj][0];
            #pragma unroll
            for (int c = 0; c < 16; c++)
                o[c] += p * vr[c*4 + g];
        }
    }

    float inv = 1.f / l;
    float* orow = out + (size_t)(b*SEQ + qg) * DIM + h * HD;
    #pragma unroll
    for (int c = 0; c < 16; c++)
        orow[c*4 + g] = o[c] * inv;
}

// =================== residual add + LayerNorm ===================
__global__ __launch_bounds__(256) void add_ln_kernel(
    const float* __restrict__ x, const float* __restrict__ a,
    const float* __restrict__ scale, const float* __restrict__ bias,
    float* __restrict__ out, int has_a) {
    int row = blockIdx.x;
    const float* xr = x + (size_t)row * DIM;
    const float* ar = a + (size_t)row * DIM;
    int t = threadIdx.x;
    float v[4];
    float s = 0.f, s2 = 0.f;
    #pragma unroll
    for (int i = 0; i < 4; i++) {
        int d = t + i*256;
        float val = xr[d] + (has_a ? ar[d] : 0.f);
        v[i] = val; s += val; s2 += val*val;
    }
    __shared__ float red[2][8];
    #pragma unroll
    for (int off = 16; off; off >>= 1) {
        s  += __shfl_xor_sync(0xffffffffu, s,  off);
        s2 += __shfl_xor_sync(0xffffffffu, s2, off);
    }
    if ((t & 31) == 0) { red[0][t>>5] = s; red[1][t>>5] = s2; }
    __syncthreads();
    float ts = 0.f, ts2 = 0.f;
    #pragma unroll
    for (int i = 0; i < 8; i++) { ts += red[0][i]; ts2 += red[1][i]; }
    float mean = ts * (1.0f/DIM);
    float var  = ts2 * (1.0f/DIM) - mean*mean;
    float inv  = rsqrtf(var + 1e-5f);
    float* orow = out + (size_t)row * DIM;
    #pragma unroll
    for (int i = 0; i < 4; i++) {
        int d = t + i*256;
        orow[d] = (v[i] - mean) * inv * scale[d] + bias[d];
    }
}

// =================== final row softmax over VOCAB (in place) ===================
__global__ __launch_bounds__(256) void softmax_kernel(float* __restrict__ out) {
    int row = blockIdx.x;
    float* r = out + (size_t)row * VOCAB;
    int t = threadIdx.x;
    float mx = -INFINITY;
    for (int i = t; i < VOCAB; i += 256) mx = fmaxf(mx, r[i]);
    __shared__ float redm[8], reds[8];
    #pragma unroll
    for (int off = 16; off; off >>= 1) mx = fmaxf(mx, __shfl_xor_sync(0xffffffffu, mx, off));
    if ((t & 31) == 0) redm[t>>5] = mx;
    __syncthreads();
    float bm = -INFINITY;
    #pragma unroll
    for (int i = 0; i < 8; i++) bm = fmaxf(bm, redm[i]);
    float sum = 0.f;
    for (int i = t; i < VOCAB; i += 256) {
        float e = expf(r[i] - bm);
        r[i] = e; sum += e;
    }
    #pragma unroll
    for (int off = 16; off; off >>= 1) sum += __shfl_xor_sync(0xffffffffu, sum, off);
    if ((t & 31) == 0) reds[t>>5] = sum;
    __syncthreads();
    float bs = 0.f;
    #pragma unroll
    for (int i = 0; i < 8; i++) bs += reds[i];
    float inv = 1.f / bs;
    for (int i = t; i < VOCAB; i += 256) r[i] *= inv;
}

// =================== launch ===================
extern "C" void kernel_launch(void* const* d_in, const int* in_sizes, int n_in,
                              void* d_out, int out_size) {
    const int*   X      = (const int*)  d_in[0];
    const float* tok    = (const float*)d_in[1];
    const float* pos    = (const float*)d_in[2];
    const float* qkv_w  = (const float*)d_in[3];
    const float* qkv_b  = (const float*)d_in[4];
    const float* out_w  = (const float*)d_in[5];
    const float* out_b  = (const float*)d_in[6];
    const float* ln1_s  = (const float*)d_in[7];
    const float* ln1_b  = (const float*)d_in[8];
    const float* ln2_s  = (const float*)d_in[9];
    const float* ln2_b  = (const float*)d_in[10];
    const float* ff1_w  = (const float*)d_in[11];
    const float* ff1_b  = (const float*)d_in[12];
    const float* ff2_w  = (const float*)d_in[13];
    const float* ff2_b  = (const float*)d_in[14];
    const float* lnf_s  = (const float*)d_in[15];
    const float* lnf_b  = (const float*)d_in[16];
    const float* head_w = (const float*)d_in[17];
    const float* head_b = (const float*)d_in[18];
    float* outp = (float*)d_out;

    float *x, *qkvb, *ao, *ff, *tmp;
    cudaGetSymbolAddress((void**)&x,    g_x);
    cudaGetSymbolAddress((void**)&qkvb, g_qkv);
    cudaGetSymbolAddress((void**)&ao,   g_ao);
    cudaGetSymbolAddress((void**)&ff,   g_ff);
    cudaGetSymbolAddress((void**)&tmp,  g_t);

    cudaFuncSetAttribute(attn_kernel, cudaFuncAttributeMaxDynamicSharedMemorySize, ATTN_SMEM);

    embed_kernel<<<ROWS, 256>>>(X, tok, pos, x);

    for (int l = 0; l < LAYERS; l++) {
        gemm_tc<0,4><<<dim3(3*DIM/128, ROWS/128), 256>>>(x, qkv_w, qkv_b, qkvb, 3*DIM, DIM);
        attn_kernel<<<dim3(SEQ/64, NH, BATCH), 256, ATTN_SMEM>>>(qkvb, ao);
        gemm_tc<0,2><<<dim3(DIM/128, ROWS/64), 256>>>(ao, out_w, out_b, tmp, DIM, DIM);
        add_ln_kernel<<<ROWS, 256>>>(x, tmp, ln1_s, ln1_b, x, 1);
        gemm_tc<1,4><<<dim3(FFD/128, ROWS/128), 256>>>(x, ff1_w, ff1_b, ff, FFD, DIM);
        gemm_tc<0,2><<<dim3(DIM/128, ROWS/64), 256>>>(ff, ff2_w, ff2_b, tmp, DIM, FFD);
        add_ln_kernel<<<ROWS, 256>>>(x, tmp, ln2_s, ln2_b, x, 1);
    }
    add_ln_kernel<<<ROWS, 256>>>(x, x, lnf_s, lnf_b, x, 0);
    gemm_tc<0,4><<<dim3(VOCAB/128, ROWS/128), 256>>>(x, head_w, head_b, outp, VOCAB, DIM);
    softmax_kernel<<<ROWS, 256>>>(outp);
}

// round 6
// speedup vs baseline: 1.8334x; 1.2061x over previous
#include <cuda_runtime.h>
#include <cuda_fp16.h>
#include <math.h>
#include <stdint.h>

#define SEQ    1024
#define DIM    1024
#define NH     16
#define HD     64
#define LAYERS 6
#define BATCH  2
#define ROWS   (BATCH*SEQ)   // 2048
#define FFD    (4*DIM)       // 4096
#define VOCAB  32000

// ---- scratch (device globals: allocation-free) ----
__device__ float    g_x   [ROWS*DIM];
__device__ __half   g_xh  [ROWS*DIM];
__device__ float    g_qkv [ROWS*3*DIM];
__device__ __half   g_aoh [ROWS*DIM];
__device__ __half   g_ffh [ROWS*FFD];
__device__ float    g_t   [ROWS*DIM];
// fp16 weights, interleaved as half2(W[2k][n], W[2k+1][n]) stored per uint32
__device__ uint32_t g_qkvwh[(DIM/2)*3*DIM];
__device__ uint32_t g_outwh[(DIM/2)*DIM];
__device__ uint32_t g_ff1wh[(DIM/2)*FFD];
__device__ uint32_t g_ff2wh[(FFD/2)*DIM];
__device__ uint32_t g_headwh[(DIM/2)*VOCAB];

__device__ __forceinline__ uint32_t packh2(float a, float b) {
    __half2 h = __floats2half2_rn(a, b);
    return *(uint32_t*)&h;
}

// =================== weight conversion (fp32 -> interleaved fp16) ===================
__global__ void convert_w(const float* __restrict__ W, uint32_t* __restrict__ Wh, int N) {
    int idx = blockIdx.x * 256 + threadIdx.x;   // over (K/2)*N
    int kk = idx / N, n = idx - kk * N;
    Wh[idx] = packh2(W[(size_t)(2*kk) * N + n], W[(size_t)(2*kk+1) * N + n]);
}

// =================== embedding (fp32 + fp16) ===================
__global__ void embed_kernel(const int* __restrict__ X, const float* __restrict__ tok,
                             const float* __restrict__ pos, float* __restrict__ x,
                             __half* __restrict__ xh) {
    int row = blockIdx.x;
    int s   = row % SEQ;
    int v   = X[row];
    const float* te = tok + (size_t)v * DIM;
    const float* pe = pos + (size_t)s * DIM;
    float*  xr  = x  + (size_t)row * DIM;
    __half* xhr = xh + (size_t)row * DIM;
    for (int d = threadIdx.x; d < DIM; d += blockDim.x) {
        float val = te[d] + pe[d];
        xr[d]  = val;
        xhr[d] = __float2half(val);
    }
}

// =================== fp16 tensor-core GEMM, 4-stage cp.async pipeline ===================
// C[M,N] = A[M,K] @ B[K,N] + bias. EPI 0: fp32 out. EPI 1: exact GELU -> fp16 out.
// MT m-tiles per warp: MT=4 -> BM=128, MT=2 -> BM=64. BN=128, BK=16. 8 warps (2x4).
__device__ __forceinline__ float gelu_exact(float v) {
    return 0.5f * v * (1.0f + erff(v * 0.70710678118654752f));
}
__device__ __forceinline__ void cp16(uint32_t dst, const void* src) {
    asm volatile("cp.async.cg.shared.global [%0], [%1], 16;\n" :: "r"(dst), "l"(src));
}

template<int EPI, int MT>
__global__ __launch_bounds__(256, MT==2 ? 3 : 2) void gemm_tc(
    const __half* __restrict__ A, const uint32_t* __restrict__ Bh,
    const float* __restrict__ bias, void* __restrict__ Cv,
    int N, int K) {
    constexpr int BM = MT * 32;
    // As2[m][kk]: half2 k-pairs of A row m, row stride 12 u32 (48B, 16B-aligned)
    // Bs2[kk][n]: interleaved weights, row stride 136 u32 (544B, 16B-aligned)
    __shared__ __align__(16) uint32_t As2[4][BM][12];
    __shared__ __align__(16) uint32_t Bs2[4][8][136];

    const int t    = threadIdx.x;
    const int warp = t >> 5, lane = t & 31;
    const int wm   = warp >> 2, wn = warp & 3;      // 2 x 4 warp grid
    const int g    = lane >> 2, tig = lane & 3;
    const int bm   = blockIdx.y * BM;
    const int bn   = blockIdx.x * 128;

    // async-copy geometry
    const int arow = t >> 1, achk = t & 1;          // A: row, 16B chunk (8 halves)
    const int brow = t >> 5, bcol = (t & 31) << 2;  // B: k-pair row, 16B chunk (4 u32)

    float acc[MT][4][4];
    #pragma unroll
    for (int i = 0; i < MT; i++)
        #pragma unroll
        for (int j = 0; j < 4; j++)
            #pragma unroll
            for (int r = 0; r < 4; r++) acc[i][j][r] = 0.f;

    const int nkt = K >> 4;

    #define ISSUE(kt_) do {                                                          \
        int stg_ = (kt_) & 3;                                                        \
        int k0_  = (kt_) << 4;                                                       \
        if (MT == 4 || t < 128) {                                                    \
            uint32_t d_ = (uint32_t)__cvta_generic_to_shared(&As2[stg_][arow][achk*4]); \
            cp16(d_, A + (size_t)(bm + arow) * K + k0_ + achk*8);                    \
        }                                                                            \
        uint32_t d2_ = (uint32_t)__cvta_generic_to_shared(&Bs2[stg_][brow][bcol]);   \
        cp16(d2_, Bh + (size_t)((k0_ >> 1) + brow) * N + bn + bcol);                 \
        asm volatile("cp.async.commit_group;\n");                                    \
    } while (0)

    ISSUE(0); ISSUE(1); ISSUE(2);

    for (int kt = 0; kt < nkt; kt++) {
        asm volatile("cp.async.wait_group 2;\n");
        __syncthreads();
        if (kt + 3 < nkt) ISSUE(kt + 3);
        else              asm volatile("cp.async.commit_group;\n");

        const int cur = kt & 3;
        uint32_t a[MT][4];
        #pragma unroll
        for (int mt = 0; mt < MT; mt++) {
            int m = wm * (MT * 16) + mt * 16 + g;
            a[mt][0] = As2[cur][m    ][tig];
            a[mt][1] = As2[cur][m + 8][tig];
            a[mt][2] = As2[cur][m    ][tig + 4];
            a[mt][3] = As2[cur][m + 8][tig + 4];
        }
        #pragma unroll
        for (int nt = 0; nt < 4; nt++) {
            int n = wn * 32 + nt * 8 + g;
            uint32_t b0 = Bs2[cur][tig    ][n];
            uint32_t b1 = Bs2[cur][tig + 4][n];
            #pragma unroll
            for (int mt = 0; mt < MT; mt++) {
                asm volatile(
                    "mma.sync.aligned.m16n8k16.row.col.f32.f16.f16.f32 "
                    "{%0,%1,%2,%3}, {%4,%5,%6,%7}, {%8,%9}, {%0,%1,%2,%3};\n"
                    : "+f"(acc[mt][nt][0]), "+f"(acc[mt][nt][1]),
                      "+f"(acc[mt][nt][2]), "+f"(acc[mt][nt][3])
                    : "r"(a[mt][0]), "r"(a[mt][1]), "r"(a[mt][2]), "r"(a[mt][3]),
                      "r"(b0), "r"(b1));
            }
        }
    }
    #undef ISSUE

    // epilogue: c0/c1 at (row g, cols 2tig,2tig+1), c2/c3 at row g+8
    #pragma unroll
    for (int nt = 0; nt < 4; nt++) {
        int n = bn + wn * 32 + nt * 8 + 2 * tig;
        float2 bv = *(const float2*)(bias + n);
        #pragma unroll
        for (int mt = 0; mt < MT; mt++) {
            int r = bm + wm * (MT * 16) + mt * 16 + g;
            float o00 = acc[mt][nt][0] + bv.x, o01 = acc[mt][nt][1] + bv.y;
            float o10 = acc[mt][nt][2] + bv.x, o11 = acc[mt][nt][3] + bv.y;
            if (EPI == 1) {
                __half* Ch = (__half*)Cv;
                o00 = gelu_exact(o00); o01 = gelu_exact(o01);
                o10 = gelu_exact(o10); o11 = gelu_exact(o11);
                *(__half2*)(Ch + (size_t)r * N + n)       = __floats2half2_rn(o00, o01);
                *(__half2*)(Ch + (size_t)(r + 8) * N + n) = __floats2half2_rn(o10, o11);
            } else {
                float* Cf = (float*)Cv;
                *(float2*)(Cf + (size_t)r * N + n)       = make_float2(o00, o01);
                *(float2*)(Cf + (size_t)(r + 8) * N + n) = make_float2(o10, o11);
            }
        }
    }
}

// =================== fused causal attention (flash-style, fp32, fp16 output) ===================
#define ATTN_SMEM (4*64*65*4)

__global__ __launch_bounds__(256) void attn_kernel(const float* __restrict__ qkv,
                                                   __half* __restrict__ out) {
    extern __shared__ float sm[];
    float (*Qs)[65] = (float(*)[65])(sm);
    float (*Ks)[65] = (float(*)[65])(sm + 64*65);
    float (*Vs)[65] = (float(*)[65])(sm + 2*64*65);
    float (*Ps)[65] = (float(*)[65])(sm + 3*64*65);
    const int qt = blockIdx.x, h = blockIdx.y, b = blockIdx.z;
    const int t  = threadIdx.x;
    const int qi = t >> 2, g = t & 3;

    const int RS = 3*DIM;
    const float* qbase = qkv + (size_t)(b*SEQ) * RS + h * (3*HD);

    #pragma unroll
    for (int i = 0; i < 4; i++) {
        int f = t + i*256;
        int r = f >> 4;
        int c = (f & 15) << 2;
        float4 v = *(const float4*)(qbase + (size_t)(qt*64 + r) * RS + c);
        Qs[r][c]=v.x; Qs[r][c+1]=v.y; Qs[r][c+2]=v.z; Qs[r][c+3]=v.w;
    }

    float m = -INFINITY, l = 0.f;
    float o[16];
    #pragma unroll
    for (int i = 0; i < 16; i++) o[i] = 0.f;
    const int qg = qt*64 + qi;

    for (int kt = 0; kt <= qt; kt++) {
        __syncthreads();
        #pragma unroll
        for (int i = 0; i < 4; i++) {
            int f = t + i*256;
            int r = f >> 4;
            int c = (f & 15) << 2;
            const float* base = qbase + (size_t)(kt*64 + r) * RS + 64 + c;
            float4 kv = *(const float4*)(base);
            Ks[r][c]=kv.x; Ks[r][c+1]=kv.y; Ks[r][c+2]=kv.z; Ks[r][c+3]=kv.w;
            float4 vv = *(const float4*)(base + 64);
            Vs[r][c]=vv.x; Vs[r][c+1]=vv.y; Vs[r][c+2]=vv.z; Vs[r][c+3]=vv.w;
        }
        __syncthreads();

        float sreg[16];
        #pragma unroll
        for (int j = 0; j < 16; j++) sreg[j] = 0.f;
        #pragma unroll
        for (int d0 = 0; d0 < 64; d0 += 16) {
            float q[16];
            #pragma unroll
            for (int dd = 0; dd < 16; dd++) q[dd] = Qs[qi][d0+dd];
            #pragma unroll
            for (int j = 0; j < 16; j++) {
                const float* kr = &Ks[j*4 + g][d0];
                #pragma unroll
                for (int dd = 0; dd < 16; dd++) sreg[j] += q[dd] * kr[dd];
            }
        }
        float tmax = -INFINITY;
        #pragma unroll
        for (int j = 0; j < 16; j++) {
            int kgl = kt*64 + j*4 + g;
            float sv = sreg[j] * 0.125f;
            if (kgl > qg) sv = -INFINITY;
            sreg[j] = sv;
            tmax = fmaxf(tmax, sv);
        }
        tmax = fmaxf(tmax, __shfl_xor_sync(0xffffffffu, tmax, 1));
        tmax = fmaxf(tmax, __shfl_xor_sync(0xffffffffu, tmax, 2));
        float nm   = fmaxf(m, tmax);
        float corr = expf(m - nm);
        m = nm;

        float lsum = 0.f;
        #pragma unroll
        for (int j = 0; j < 16; j++) {
            float p = expf(sreg[j] - m);
            lsum += p;
            Ps[qi][j*4 + g] = p;
        }
        lsum += __shfl_xor_sync(0xffffffffu, lsum, 1);
        lsum += __shfl_xor_sync(0xffffffffu, lsum, 2);
        l = l * corr + lsum;
        #pragma unroll
        for (int c = 0; c < 16; c++) o[c] *= corr;
        __syncwarp();

        for (int kj = 0; kj < 64; kj++) {
            float p = Ps[qi][kj];
            const float* vr = &Vs[kj][0];
            #pragma unroll
            for (int c = 0; c < 16; c++)
                o[c] += p * vr[c*4 + g];
        }
    }

    float inv = 1.f / l;
    __half* orow = out + (size_t)(b*SEQ + qg) * DIM + h * HD;
    #pragma unroll
    for (int c = 0; c < 16; c++)
        orow[c*4 + g] = __float2half(o[c] * inv);
}

// =================== residual add + LayerNorm (fp32 + fp16 out) ===================
__global__ __launch_bounds__(256) void add_ln_kernel(
    const float* __restrict__ x, const float* __restrict__ a,
    const float* __restrict__ scale, const float* __restrict__ bias,
    float* __restrict__ out, __half* __restrict__ outh, int has_a) {
    int row = blockIdx.x;
    const float* xr = x + (size_t)row * DIM;
    const float* ar = a + (size_t)row * DIM;
    int t = threadIdx.x;
    float v[4];
    float s = 0.f, s2 = 0.f;
    #pragma unroll
    for (int i = 0; i < 4; i++) {
        int d = t + i*256;
        float val = xr[d] + (has_a ? ar[d] : 0.f);
        v[i] = val; s += val; s2 += val*val;
    }
    __shared__ float red[2][8];
    #pragma unroll
    for (int off = 16; off; off >>= 1) {
        s  += __shfl_xor_sync(0xffffffffu, s,  off);
        s2 += __shfl_xor_sync(0xffffffffu, s2, off);
    }
    if ((t & 31) == 0) { red[0][t>>5] = s; red[1][t>>5] = s2; }
    __syncthreads();
    float ts = 0.f, ts2 = 0.f;
    #pragma unroll
    for (int i = 0; i < 8; i++) { ts += red[0][i]; ts2 += red[1][i]; }
    float mean = ts * (1.0f/DIM);
    float var  = ts2 * (1.0f/DIM) - mean*mean;
    float inv  = rsqrtf(var + 1e-5f);
    float*  orow  = out  + (size_t)row * DIM;
    __half* orowh = outh + (size_t)row * DIM;
    #pragma unroll
    for (int i = 0; i < 4; i++) {
        int d = t + i*256;
        float val = (v[i] - mean) * inv * scale[d] + bias[d];
        orow[d]  = val;
        orowh[d] = __float2half(val);
    }
}

// =================== final row softmax over VOCAB (in place) ===================
__global__ __launch_bounds__(256) void softmax_kernel(float* __restrict__ out) {
    int row = blockIdx.x;
    float* r = out + (size_t)row * VOCAB;
    int t = threadIdx.x;
    float mx = -INFINITY;
    for (int i = t; i < VOCAB; i += 256) mx = fmaxf(mx, r[i]);
    __shared__ float redm[8], reds[8];
    #pragma unroll
    for (int off = 16; off; off >>= 1) mx = fmaxf(mx, __shfl_xor_sync(0xffffffffu, mx, off));
    if ((t & 31) == 0) redm[t>>5] = mx;
    __syncthreads();
    float bm = -INFINITY;
    #pragma unroll
    for (int i = 0; i < 8; i++) bm = fmaxf(bm, redm[i]);
    float sum = 0.f;
    for (int i = t; i < VOCAB; i += 256) {
        float e = expf(r[i] - bm);
        r[i] = e; sum += e;
    }
    #pragma unroll
    for (int off = 16; off; off >>= 1) sum += __shfl_xor_sync(0xffffffffu, sum, off);
    if ((t & 31) == 0) reds[t>>5] = sum;
    __syncthreads();
    float bs = 0.f;
    #pragma unroll
    for (int i = 0; i < 8; i++) bs += reds[i];
    float inv = 1.f / bs;
    for (int i = t; i < VOCAB; i += 256) r[i] *= inv;
}

// =================== launch ===================
extern "C" void kernel_launch(void* const* d_in, const int* in_sizes, int n_in,
                              void* d_out, int out_size) {
    const int*   X      = (const int*)  d_in[0];
    const float* tok    = (const float*)d_in[1];
    const float* pos    = (const float*)d_in[2];
    const float* qkv_w  = (const float*)d_in[3];
    const float* qkv_b  = (const float*)d_in[4];
    const float* out_w  = (const float*)d_in[5];
    const float* out_b  = (const float*)d_in[6];
    const float* ln1_s  = (const float*)d_in[7];
    const float* ln1_b  = (const float*)d_in[8];
    const float* ln2_s  = (const float*)d_in[9];
    const float* ln2_b  = (const float*)d_in[10];
    const float* ff1_w  = (const float*)d_in[11];
    const float* ff1_b  = (const float*)d_in[12];
    const float* ff2_w  = (const float*)d_in[13];
    const float* ff2_b  = (const float*)d_in[14];
    const float* lnf_s  = (const float*)d_in[15];
    const float* lnf_b  = (const float*)d_in[16];
    const float* head_w = (const float*)d_in[17];
    const float* head_b = (const float*)d_in[18];
    float* outp = (float*)d_out;

    float *x, *qkvb, *tmp;
    __half *xh, *aoh, *ffh;
    uint32_t *qkvwh, *outwh, *ff1wh, *ff2wh, *headwh;
    cudaGetSymbolAddress((void**)&x,     g_x);
    cudaGetSymbolAddress((void**)&xh,    g_xh);
    cudaGetSymbolAddress((void**)&qkvb,  g_qkv);
    cudaGetSymbolAddress((void**)&aoh,   g_aoh);
    cudaGetSymbolAddress((void**)&ffh,   g_ffh);
    cudaGetSymbolAddress((void**)&tmp,   g_t);
    cudaGetSymbolAddress((void**)&qkvwh, g_qkvwh);
    cudaGetSymbolAddress((void**)&outwh, g_outwh);
    cudaGetSymbolAddress((void**)&ff1wh, g_ff1wh);
    cudaGetSymbolAddress((void**)&ff2wh, g_ff2wh);
    cudaGetSymbolAddress((void**)&headwh, g_headwh);

    cudaFuncSetAttribute(attn_kernel, cudaFuncAttributeMaxDynamicSharedMemorySize, ATTN_SMEM);

    // one-time weight conversions (per launch)
    convert_w<<<(DIM/2)*3*DIM/256, 256>>>(qkv_w,  qkvwh,  3*DIM);
    convert_w<<<(DIM/2)*DIM/256,   256>>>(out_w,  outwh,  DIM);
    convert_w<<<(DIM/2)*FFD/256,   256>>>(ff1_w,  ff1wh,  FFD);
    convert_w<<<(FFD/2)*DIM/256,   256>>>(ff2_w,  ff2wh,  DIM);
    convert_w<<<(DIM/2)*VOCAB/256, 256>>>(head_w, headwh, VOCAB);

    embed_kernel<<<ROWS, 256>>>(X, tok, pos, x, xh);

    for (int l = 0; l < LAYERS; l++) {
        gemm_tc<0,4><<<dim3(3*DIM/128, ROWS/128), 256>>>(xh, qkvwh, qkv_b, qkvb, 3*DIM, DIM);
        attn_kernel<<<dim3(SEQ/64, NH, BATCH), 256, ATTN_SMEM>>>(qkvb, aoh);
        gemm_tc<0,2><<<dim3(DIM/128, ROWS/64), 256>>>(aoh, outwh, out_b, tmp, DIM, DIM);
        add_ln_kernel<<<ROWS, 256>>>(x, tmp, ln1_s, ln1_b, x, xh, 1);
        gemm_tc<1,4><<<dim3(FFD/128, ROWS/128), 256>>>(xh, ff1wh, ff1_b, ffh, FFD, DIM);
        gemm_tc<0,2><<<dim3(DIM/128, ROWS/64), 256>>>(ffh, ff2wh, ff2_b, tmp, DIM, FFD);
        add_ln_kernel<<<ROWS, 256>>>(x, tmp, ln2_s, ln2_b, x, xh, 1);
    }
    add_ln_kernel<<<ROWS, 256>>>(x, x, lnf_s, lnf_b, x, xh, 0);
    gemm_tc<0,4><<<dim3(VOCAB/128, ROWS/128), 256>>>(xh, headwh, head_b, outp, VOCAB, DIM);
    softmax_kernel<<<ROWS, 256>>>(outp);
}

// round 7
// speedup vs baseline: 3.4433x; 1.8781x over previous
#include <cuda_runtime.h>
#include <cuda_fp16.h>
#include <math.h>
#include <stdint.h>

#define SEQ    1024
#define DIM    1024
#define NH     16
#define HD     64
#define LAYERS 6
#define BATCH  2
#define ROWS   (BATCH*SEQ)   // 2048
#define FFD    (4*DIM)       // 4096
#define VOCAB  32000

// ---- scratch (device globals: allocation-free) ----
__device__ float    g_x   [ROWS*DIM];
__device__ __half   g_xh  [ROWS*DIM];
__device__ __half   g_qkvh[ROWS*3*DIM];
__device__ __half   g_aoh [ROWS*DIM];
__device__ __half   g_ffh [ROWS*FFD];
__device__ float    g_t   [ROWS*DIM];
// fp16 weights, interleaved as half2(W[2k][n], W[2k+1][n]) stored per uint32
__device__ uint32_t g_qkvwh[(DIM/2)*3*DIM];
__device__ uint32_t g_outwh[(DIM/2)*DIM];
__device__ uint32_t g_ff1wh[(DIM/2)*FFD];
__device__ uint32_t g_ff2wh[(FFD/2)*DIM];
__device__ uint32_t g_headwh[(DIM/2)*VOCAB];

__device__ __forceinline__ uint32_t packh2(float a, float b) {
    __half2 h = __floats2half2_rn(a, b);
    return *(uint32_t*)&h;
}

// =================== weight conversion (fp32 -> interleaved fp16) ===================
__global__ void convert_w(const float* __restrict__ W, uint32_t* __restrict__ Wh, int N) {
    int idx = blockIdx.x * 256 + threadIdx.x;   // over (K/2)*N
    int kk = idx / N, n = idx - kk * N;
    Wh[idx] = packh2(W[(size_t)(2*kk) * N + n], W[(size_t)(2*kk+1) * N + n]);
}

// =================== embedding (fp32 + fp16) ===================
__global__ void embed_kernel(const int* __restrict__ X, const float* __restrict__ tok,
                             const float* __restrict__ pos, float* __restrict__ x,
                             __half* __restrict__ xh) {
    int row = blockIdx.x;
    int s   = row % SEQ;
    int v   = X[row];
    const float* te = tok + (size_t)v * DIM;
    const float* pe = pos + (size_t)s * DIM;
    float*  xr  = x  + (size_t)row * DIM;
    __half* xhr = xh + (size_t)row * DIM;
    for (int d = threadIdx.x; d < DIM; d += blockDim.x) {
        float val = te[d] + pe[d];
        xr[d]  = val;
        xhr[d] = __float2half(val);
    }
}

// =================== fp16 tensor-core GEMM, 4-stage cp.async pipeline ===================
// EPI 0: fp32 out. EPI 1: GELU -> fp16 out. EPI 2: bias-only -> fp16 out.
__device__ __forceinline__ float gelu_exact(float v) {
    return 0.5f * v * (1.0f + erff(v * 0.70710678118654752f));
}
__device__ __forceinline__ void cp16(uint32_t dst, const void* src) {
    asm volatile("cp.async.cg.shared.global [%0], [%1], 16;\n" :: "r"(dst), "l"(src));
}

template<int EPI, int MT>
__global__ __launch_bounds__(256, MT==2 ? 3 : 2) void gemm_tc(
    const __half* __restrict__ A, const uint32_t* __restrict__ Bh,
    const float* __restrict__ bias, void* __restrict__ Cv,
    int N, int K) {
    constexpr int BM = MT * 32;
    __shared__ __align__(16) uint32_t As2[4][BM][12];
    __shared__ __align__(16) uint32_t Bs2[4][8][136];

    const int t    = threadIdx.x;
    const int warp = t >> 5, lane = t & 31;
    const int wm   = warp >> 2, wn = warp & 3;      // 2 x 4 warp grid
    const int g    = lane >> 2, tig = lane & 3;
    const int bm   = blockIdx.y * BM;
    const int bn   = blockIdx.x * 128;

    const int arow = t >> 1, achk = t & 1;
    const int brow = t >> 5, bcol = (t & 31) << 2;

    float acc[MT][4][4];
    #pragma unroll
    for (int i = 0; i < MT; i++)
        #pragma unroll
        for (int j = 0; j < 4; j++)
            #pragma unroll
            for (int r = 0; r < 4; r++) acc[i][j][r] = 0.f;

    const int nkt = K >> 4;

    #define ISSUE(kt_) do {                                                          \
        int stg_ = (kt_) & 3;                                                        \
        int k0_  = (kt_) << 4;                                                       \
        if (MT == 4 || t < 128) {                                                    \
            uint32_t d_ = (uint32_t)__cvta_generic_to_shared(&As2[stg_][arow][achk*4]); \
            cp16(d_, A + (size_t)(bm + arow) * K + k0_ + achk*8);                    \
        }                                                                            \
        uint32_t d2_ = (uint32_t)__cvta_generic_to_shared(&Bs2[stg_][brow][bcol]);   \
        cp16(d2_, Bh + (size_t)((k0_ >> 1) + brow) * N + bn + bcol);                 \
        asm volatile("cp.async.commit_group;\n");                                    \
    } while (0)

    ISSUE(0); ISSUE(1); ISSUE(2);

    for (int kt = 0; kt < nkt; kt++) {
        asm volatile("cp.async.wait_group 2;\n");
        __syncthreads();
        if (kt + 3 < nkt) ISSUE(kt + 3);
        else              asm volatile("cp.async.commit_group;\n");

        const int cur = kt & 3;
        uint32_t a[MT][4];
        #pragma unroll
        for (int mt = 0; mt < MT; mt++) {
            int m = wm * (MT * 16) + mt * 16 + g;
            a[mt][0] = As2[cur][m    ][tig];
            a[mt][1] = As2[cur][m + 8][tig];
            a[mt][2] = As2[cur][m    ][tig + 4];
            a[mt][3] = As2[cur][m + 8][tig + 4];
        }
        #pragma unroll
        for (int nt = 0; nt < 4; nt++) {
            int n = wn * 32 + nt * 8 + g;
            uint32_t b0 = Bs2[cur][tig    ][n];
            uint32_t b1 = Bs2[cur][tig + 4][n];
            #pragma unroll
            for (int mt = 0; mt < MT; mt++) {
                asm volatile(
                    "mma.sync.aligned.m16n8k16.row.col.f32.f16.f16.f32 "
                    "{%0,%1,%2,%3}, {%4,%5,%6,%7}, {%8,%9}, {%0,%1,%2,%3};\n"
                    : "+f"(acc[mt][nt][0]), "+f"(acc[mt][nt][1]),
                      "+f"(acc[mt][nt][2]), "+f"(acc[mt][nt][3])
                    : "r"(a[mt][0]), "r"(a[mt][1]), "r"(a[mt][2]), "r"(a[mt][3]),
                      "r"(b0), "r"(b1));
            }
        }
    }
    #undef ISSUE

    #pragma unroll
    for (int nt = 0; nt < 4; nt++) {
        int n = bn + wn * 32 + nt * 8 + 2 * tig;
        float2 bv = *(const float2*)(bias + n);
        #pragma unroll
        for (int mt = 0; mt < MT; mt++) {
            int r = bm + wm * (MT * 16) + mt * 16 + g;
            float o00 = acc[mt][nt][0] + bv.x, o01 = acc[mt][nt][1] + bv.y;
            float o10 = acc[mt][nt][2] + bv.x, o11 = acc[mt][nt][3] + bv.y;
            if (EPI == 1) {
                o00 = gelu_exact(o00); o01 = gelu_exact(o01);
                o10 = gelu_exact(o10); o11 = gelu_exact(o11);
            }
            if (EPI >= 1) {
                __half* Ch = (__half*)Cv;
                *(__half2*)(Ch + (size_t)r * N + n)       = __floats2half2_rn(o00, o01);
                *(__half2*)(Ch + (size_t)(r + 8) * N + n) = __floats2half2_rn(o10, o11);
            } else {
                float* Cf = (float*)Cv;
                *(float2*)(Cf + (size_t)r * N + n)       = make_float2(o00, o01);
                *(float2*)(Cf + (size_t)(r + 8) * N + n) = make_float2(o10, o11);
            }
        }
    }
}

// =================== tensor-core flash attention (fp16 mma, fp32 softmax/acc) ===================
// block = (qt, h, b), 128 threads = 4 warps; warp w owns q rows qt*64 + w*16 + [0,16).
__global__ __launch_bounds__(128) void attn_kernel(const __half* __restrict__ qkvh,
                                                   __half* __restrict__ out) {
    __shared__ __align__(16) __half   Qs[64][72];
    __shared__ __align__(16) __half   Ks[64][72];
    __shared__ __align__(16) uint32_t Vs2[32][68];   // half2(V[2s][d], V[2s+1][d])

    const int qt = blockIdx.x, h = blockIdx.y, b = blockIdx.z;
    const int t  = threadIdx.x;
    const int w  = t >> 5, lane = t & 31;
    const int g  = lane >> 2, tig = lane & 3;
    const int RS = 3*DIM;
    const __half* base = qkvh + (size_t)(b*SEQ) * RS + h * (3*HD);

    // load Q tile (64x64 halves)
    #pragma unroll
    for (int i = 0; i < 4; i++) {
        int f = t + i*128;
        int r = f >> 3, c = (f & 7) << 3;
        *(uint4*)&Qs[r][c] = *(const uint4*)(base + (size_t)(qt*64 + r) * RS + c);
    }
    __syncthreads();

    // Q fragments (A-operand), 4 k-chunks of 16
    uint32_t qf[4][4];
    {
        const __half* r0 = &Qs[w*16 + g    ][0];
        const __half* r8 = &Qs[w*16 + g + 8][0];
        #pragma unroll
        for (int kc = 0; kc < 4; kc++) {
            qf[kc][0] = *(const uint32_t*)(r0 + kc*16 + 2*tig);
            qf[kc][1] = *(const uint32_t*)(r8 + kc*16 + 2*tig);
            qf[kc][2] = *(const uint32_t*)(r0 + kc*16 + 8 + 2*tig);
            qf[kc][3] = *(const uint32_t*)(r8 + kc*16 + 8 + 2*tig);
        }
    }

    float m0 = -INFINITY, m1 = -INFINITY, l0 = 0.f, l1 = 0.f;
    float o[8][4];
    #pragma unroll
    for (int i = 0; i < 8; i++)
        #pragma unroll
        for (int j = 0; j < 4; j++) o[i][j] = 0.f;

    const int q0 = qt*64 + w*16 + g;       // row for c0/c1
    const int q1 = q0 + 8;                 // row for c2/c3

    for (int kt = 0; kt <= qt; kt++) {
        __syncthreads();
        // load K tile
        #pragma unroll
        for (int i = 0; i < 4; i++) {
            int f = t + i*128;
            int r = f >> 3, c = (f & 7) << 3;
            *(uint4*)&Ks[r][c] = *(const uint4*)(base + (size_t)(kt*64 + r) * RS + 64 + c);
        }
        // load V tile, interleaved over s-pairs
        #pragma unroll
        for (int i = 0; i < 2; i++) {
            int f = t + i*128;
            int rp = f >> 3, c = (f & 7) << 3;
            const __half* v0 = base + (size_t)(kt*64 + 2*rp) * RS + 128 + c;
            uint4 lo = *(const uint4*)v0;
            uint4 hi = *(const uint4*)(v0 + RS);
            const ushort* ls = (const ushort*)&lo;
            const ushort* hs = (const ushort*)&hi;
            uint32_t pk[8];
            #pragma unroll
            for (int j = 0; j < 8; j++) pk[j] = (uint32_t)ls[j] | ((uint32_t)hs[j] << 16);
            *(uint4*)&Vs2[rp][c]     = make_uint4(pk[0], pk[1], pk[2], pk[3]);
            *(uint4*)&Vs2[rp][c + 4] = make_uint4(pk[4], pk[5], pk[6], pk[7]);
        }
        __syncthreads();

        // S = Q @ K^T  (8 n-tiles of 8 s-cols)
        float s[8][4];
        #pragma unroll
        for (int i = 0; i < 8; i++)
            #pragma unroll
            for (int j = 0; j < 4; j++) s[i][j] = 0.f;
        #pragma unroll
        for (int kc = 0; kc < 4; kc++) {
            #pragma unroll
            for (int nt = 0; nt < 8; nt++) {
                uint32_t b0 = *(const uint32_t*)(&Ks[nt*8 + g][kc*16 + 2*tig]);
                uint32_t b1 = *(const uint32_t*)(&Ks[nt*8 + g][kc*16 + 8 + 2*tig]);
                asm volatile(
                    "mma.sync.aligned.m16n8k16.row.col.f32.f16.f16.f32 "
                    "{%0,%1,%2,%3}, {%4,%5,%6,%7}, {%8,%9}, {%0,%1,%2,%3};\n"
                    : "+f"(s[nt][0]), "+f"(s[nt][1]), "+f"(s[nt][2]), "+f"(s[nt][3])
                    : "r"(qf[kc][0]), "r"(qf[kc][1]), "r"(qf[kc][2]), "r"(qf[kc][3]),
                      "r"(b0), "r"(b1));
            }
        }

        // scale + causal mask + tile row-max
        float tm0 = -INFINITY, tm1 = -INFINITY;
        #pragma unroll
        for (int nt = 0; nt < 8; nt++) {
            int c0 = kt*64 + nt*8 + 2*tig, c1 = c0 + 1;
            s[nt][0] = (c0 <= q0) ? s[nt][0] * 0.125f : -INFINITY;
            s[nt][1] = (c1 <= q0) ? s[nt][1] * 0.125f : -INFINITY;
            s[nt][2] = (c0 <= q1) ? s[nt][2] * 0.125f : -INFINITY;
            s[nt][3] = (c1 <= q1) ? s[nt][3] * 0.125f : -INFINITY;
            tm0 = fmaxf(tm0, fmaxf(s[nt][0], s[nt][1]));
            tm1 = fmaxf(tm1, fmaxf(s[nt][2], s[nt][3]));
        }
        tm0 = fmaxf(tm0, __shfl_xor_sync(0xffffffffu, tm0, 1));
        tm0 = fmaxf(tm0, __shfl_xor_sync(0xffffffffu, tm0, 2));
        tm1 = fmaxf(tm1, __shfl_xor_sync(0xffffffffu, tm1, 1));
        tm1 = fmaxf(tm1, __shfl_xor_sync(0xffffffffu, tm1, 2));

        float nm0 = fmaxf(m0, tm0), nm1 = fmaxf(m1, tm1);
        float corr0 = expf(m0 - nm0), corr1 = expf(m1 - nm1);
        m0 = nm0; m1 = nm1;

        // exponentiate, pack P fragments (A-operand for PV)
        uint32_t pf[4][4];
        float ls0 = 0.f, ls1 = 0.f;
        #pragma unroll
        for (int j = 0; j < 4; j++) {
            float p00 = expf(s[2*j][0]   - m0), p01 = expf(s[2*j][1]   - m0);
            float p02 = expf(s[2*j][2]   - m1), p03 = expf(s[2*j][3]   - m1);
            float p10 = expf(s[2*j+1][0] - m0), p11 = expf(s[2*j+1][1] - m0);
            float p12 = expf(s[2*j+1][2] - m1), p13 = expf(s[2*j+1][3] - m1);
            ls0 += p00 + p01 + p10 + p11;
            ls1 += p02 + p03 + p12 + p13;
            pf[j][0] = packh2(p00, p01);
            pf[j][1] = packh2(p02, p03);
            pf[j][2] = packh2(p10, p11);
            pf[j][3] = packh2(p12, p13);
        }
        ls0 += __shfl_xor_sync(0xffffffffu, ls0, 1);
        ls0 += __shfl_xor_sync(0xffffffffu, ls0, 2);
        ls1 += __shfl_xor_sync(0xffffffffu, ls1, 1);
        ls1 += __shfl_xor_sync(0xffffffffu, ls1, 2);
        l0 = l0 * corr0 + ls0;
        l1 = l1 * corr1 + ls1;

        // rescale O
        #pragma unroll
        for (int nt = 0; nt < 8; nt++) {
            o[nt][0] *= corr0; o[nt][1] *= corr0;
            o[nt][2] *= corr1; o[nt][3] *= corr1;
        }

        // O += P @ V   (k over s in 4 chunks of 16)
        #pragma unroll
        for (int j = 0; j < 4; j++) {
            #pragma unroll
            for (int nt = 0; nt < 8; nt++) {
                uint32_t b0 = Vs2[8*j + tig    ][nt*8 + g];
                uint32_t b1 = Vs2[8*j + tig + 4][nt*8 + g];
                asm volatile(
                    "mma.sync.aligned.m16n8k16.row.col.f32.f16.f16.f32 "
                    "{%0,%1,%2,%3}, {%4,%5,%6,%7}, {%8,%9}, {%0,%1,%2,%3};\n"
                    : "+f"(o[nt][0]), "+f"(o[nt][1]), "+f"(o[nt][2]), "+f"(o[nt][3])
                    : "r"(pf[j][0]), "r"(pf[j][1]), "r"(pf[j][2]), "r"(pf[j][3]),
                      "r"(b0), "r"(b1));
            }
        }
    }

    float inv0 = 1.f / l0, inv1 = 1.f / l1;
    __half* or0 = out + (size_t)(b*SEQ + q0) * DIM + h * HD;
    __half* or1 = out + (size_t)(b*SEQ + q1) * DIM + h * HD;
    #pragma unroll
    for (int nt = 0; nt < 8; nt++) {
        int c = nt*8 + 2*tig;
        *(__half2*)(or0 + c) = __floats2half2_rn(o[nt][0] * inv0, o[nt][1] * inv0);
        *(__half2*)(or1 + c) = __floats2half2_rn(o[nt][2] * inv1, o[nt][3] * inv1);
    }
}

// =================== residual add + LayerNorm (fp32 + fp16 out) ===================
__global__ __launch_bounds__(256) void add_ln_kernel(
    const float* __restrict__ x, const float* __restrict__ a,
    const float* __restrict__ scale, const float* __restrict__ bias,
    float* __restrict__ out, __half* __restrict__ outh, int has_a) {
    int row = blockIdx.x;
    const float* xr = x + (size_t)row * DIM;
    const float* ar = a + (size_t)row * DIM;
    int t = threadIdx.x;
    float v[4];
    float s = 0.f, s2 = 0.f;
    #pragma unroll
    for (int i = 0; i < 4; i++) {
        int d = t + i*256;
        float val = xr[d] + (has_a ? ar[d] : 0.f);
        v[i] = val; s += val; s2 += val*val;
    }
    __shared__ float red[2][8];
    #pragma unroll
    for (int off = 16; off; off >>= 1) {
        s  += __shfl_xor_sync(0xffffffffu, s,  off);
        s2 += __shfl_xor_sync(0xffffffffu, s2, off);
    }
    if ((t & 31) == 0) { red[0][t>>5] = s; red[1][t>>5] = s2; }
    __syncthreads();
    float ts = 0.f, ts2 = 0.f;
    #pragma unroll
    for (int i = 0; i < 8; i++) { ts += red[0][i]; ts2 += red[1][i]; }
    float mean = ts * (1.0f/DIM);
    float var  = ts2 * (1.0f/DIM) - mean*mean;
    float inv  = rsqrtf(var + 1e-5f);
    float*  orow  = out  + (size_t)row * DIM;
    __half* orowh = outh + (size_t)row * DIM;
    #pragma unroll
    for (int i = 0; i < 4; i++) {
        int d = t + i*256;
        float val = (v[i] - mean) * inv * scale[d] + bias[d];
        orow[d]  = val;
        orowh[d] = __float2half(val);
    }
}

// =================== final row softmax over VOCAB (in place) ===================
__global__ __launch_bounds__(256) void softmax_kernel(float* __restrict__ out) {
    int row = blockIdx.x;
    float* r = out + (size_t)row * VOCAB;
    int t = threadIdx.x;
    float mx = -INFINITY;
    for (int i = t; i < VOCAB; i += 256) mx = fmaxf(mx, r[i]);
    __shared__ float redm[8], reds[8];
    #pragma unroll
    for (int off = 16; off; off >>= 1) mx = fmaxf(mx, __shfl_xor_sync(0xffffffffu, mx, off));
    if ((t & 31) == 0) redm[t>>5] = mx;
    __syncthreads();
    float bm = -INFINITY;
    #pragma unroll
    for (int i = 0; i < 8; i++) bm = fmaxf(bm, redm[i]);
    float sum = 0.f;
    for (int i = t; i < VOCAB; i += 256) {
        float e = expf(r[i] - bm);
        r[i] = e; sum += e;
    }
    #pragma unroll
    for (int off = 16; off; off >>= 1) sum += __shfl_xor_sync(0xffffffffu, sum, off);
    if ((t & 31) == 0) reds[t>>5] = sum;
    __syncthreads();
    float bs = 0.f;
    #pragma unroll
    for (int i = 0; i < 8; i++) bs += reds[i];
    float inv = 1.f / bs;
    for (int i = t; i < VOCAB; i += 256) r[i] *= inv;
}

// =================== launch ===================
extern "C" void kernel_launch(void* const* d_in, const int* in_sizes, int n_in,
                              void* d_out, int out_size) {
    const int*   X      = (const int*)  d_in[0];
    const float* tok    = (const float*)d_in[1];
    const float* pos    = (const float*)d_in[2];
    const float* qkv_w  = (const float*)d_in[3];
    const float* qkv_b  = (const float*)d_in[4];
    const float* out_w  = (const float*)d_in[5];
    const float* out_b  = (const float*)d_in[6];
    const float* ln1_s  = (const float*)d_in[7];
    const float* ln1_b  = (const float*)d_in[8];
    const float* ln2_s  = (const float*)d_in[9];
    const float* ln2_b  = (const float*)d_in[10];
    const float* ff1_w  = (const float*)d_in[11];
    const float* ff1_b  = (const float*)d_in[12];
    const float* ff2_w  = (const float*)d_in[13];
    const float* ff2_b  = (const float*)d_in[14];
    const float* lnf_s  = (const float*)d_in[15];
    const float* lnf_b  = (const float*)d_in[16];
    const float* head_w = (const float*)d_in[17];
    const float* head_b = (const float*)d_in[18];
    float* outp = (float*)d_out;

    float *x, *tmp;
    __half *xh, *qkvh, *aoh, *ffh;
    uint32_t *qkvwh, *outwh, *ff1wh, *ff2wh, *headwh;
    cudaGetSymbolAddress((void**)&x,     g_x);
    cudaGetSymbolAddress((void**)&xh,    g_xh);
    cudaGetSymbolAddress((void**)&qkvh,  g_qkvh);
    cudaGetSymbolAddress((void**)&aoh,   g_aoh);
    cudaGetSymbolAddress((void**)&ffh,   g_ffh);
    cudaGetSymbolAddress((void**)&tmp,   g_t);
    cudaGetSymbolAddress((void**)&qkvwh, g_qkvwh);
    cudaGetSymbolAddress((void**)&outwh, g_outwh);
    cudaGetSymbolAddress((void**)&ff1wh, g_ff1wh);
    cudaGetSymbolAddress((void**)&ff2wh, g_ff2wh);
    cudaGetSymbolAddress((void**)&headwh, g_headwh);

    // one-time weight conversions (per launch)
    convert_w<<<(DIM/2)*3*DIM/256, 256>>>(qkv_w,  qkvwh,  3*DIM);
    convert_w<<<(DIM/2)*DIM/256,   256>>>(out_w,  outwh,  DIM);
    convert_w<<<(DIM/2)*FFD/256,   256>>>(ff1_w,  ff1wh,  FFD);
    convert_w<<<(FFD/2)*DIM/256,   256>>>(ff2_w,  ff2wh,  DIM);
    convert_w<<<(DIM/2)*VOCAB/256, 256>>>(head_w, headwh, VOCAB);

    embed_kernel<<<ROWS, 256>>>(X, tok, pos, x, xh);

    for (int l = 0; l < LAYERS; l++) {
        gemm_tc<2,4><<<dim3(3*DIM/128, ROWS/128), 256>>>(xh, qkvwh, qkv_b, qkvh, 3*DIM, DIM);
        attn_kernel<<<dim3(SEQ/64, NH, BATCH), 128>>>(qkvh, aoh);
        gemm_tc<0,2><<<dim3(DIM/128, ROWS/64), 256>>>(aoh, outwh, out_b, tmp, DIM, DIM);
        add_ln_kernel<<<ROWS, 256>>>(x, tmp, ln1_s, ln1_b, x, xh, 1);
        gemm_tc<1,4><<<dim3(FFD/128, ROWS/128), 256>>>(xh, ff1wh, ff1_b, ffh, FFD, DIM);
        gemm_tc<0,2><<<dim3(DIM/128, ROWS/64), 256>>>(ffh, ff2wh, ff2_b, tmp, DIM, FFD);
        add_ln_kernel<<<ROWS, 256>>>(x, tmp, ln2_s, ln2_b, x, xh, 1);
    }
    add_ln_kernel<<<ROWS, 256>>>(x, x, lnf_s, lnf_b, x, xh, 0);
    gemm_tc<0,4><<<dim3(VOCAB/128, ROWS/128), 256>>>(xh, headwh, head_b, outp, VOCAB, DIM);
    softmax_kernel<<<ROWS, 256>>>(outp);
}

// round 9
// speedup vs baseline: 3.4967x; 1.0155x over previous
#include <cuda_runtime.h>
#include <cuda_fp16.h>
#include <math.h>
#include <stdint.h>

#define SEQ    1024
#define DIM    1024
#define NH     16
#define HD     64
#define LAYERS 6
#define BATCH  2
#define ROWS   (BATCH*SEQ)   // 2048
#define FFD    (4*DIM)       // 4096
#define VOCAB  32000

// ---- scratch (device globals: allocation-free) ----
__device__ float    g_x   [ROWS*DIM];
__device__ __half   g_xh  [ROWS*DIM];
__device__ __half   g_qkvh[ROWS*3*DIM];
__device__ __half   g_aoh [ROWS*DIM];
__device__ __half   g_ffh [ROWS*FFD];
__device__ float    g_t   [ROWS*DIM];
__device__ float    g_rowsum[ROWS];
// fp16 weights, interleaved as half2(W[2k][n], W[2k+1][n]) stored per uint32
__device__ uint32_t g_qkvwh[(DIM/2)*3*DIM];
__device__ uint32_t g_outwh[(DIM/2)*DIM];
__device__ uint32_t g_ff1wh[(DIM/2)*FFD];
__device__ uint32_t g_ff2wh[(FFD/2)*DIM];
__device__ uint32_t g_headwh[(size_t)(DIM/2)*VOCAB];

__device__ __forceinline__ uint32_t packh2(float a, float b) {
    __half2 h = __floats2half2_rn(a, b);
    return *(uint32_t*)&h;
}

// =================== weight conversion (fp32 -> interleaved fp16) ===================
__global__ void convert_w(const float* __restrict__ W, uint32_t* __restrict__ Wh, int N) {
    int idx = blockIdx.x * 256 + threadIdx.x;   // over (K/2)*N
    int kk = idx / N, n = idx - kk * N;
    Wh[idx] = packh2(W[(size_t)(2*kk) * N + n], W[(size_t)(2*kk+1) * N + n]);
}

// =================== embedding (fp32 + fp16) ===================
__global__ void embed_kernel(const int* __restrict__ X, const float* __restrict__ tok,
                             const float* __restrict__ pos, float* __restrict__ x,
                             __half* __restrict__ xh) {
    int row = blockIdx.x;
    int s   = row % SEQ;
    int v   = X[row];
    const float* te = tok + (size_t)v * DIM;
    const float* pe = pos + (size_t)s * DIM;
    float*  xr  = x  + (size_t)row * DIM;
    __half* xhr = xh + (size_t)row * DIM;
    for (int d = threadIdx.x; d < DIM; d += blockDim.x) {
        float val = te[d] + pe[d];
        xr[d]  = val;
        xhr[d] = __float2half(val);
    }
}

// =================== fp16 tensor-core GEMM, 4-stage cp.async, BK=32 ===================
// EPI 0: fp32 out. EPI 1: GELU -> fp16. EPI 2: bias-only -> fp16.
// EPI 3: exp(logit+bias) -> fp32 + atomic row sums (fused softmax numerator).
__device__ __forceinline__ float gelu_exact(float v) {
    return 0.5f * v * (1.0f + erff(v * 0.70710678118654752f));
}
__device__ __forceinline__ void cp16(uint32_t dst, const void* src) {
    asm volatile("cp.async.cg.shared.global [%0], [%1], 16;\n" :: "r"(dst), "l"(src));
}

#define GEMM_SMEM_MT4 (4 * (2*128*12 + 2*8*136) * 4)   // 83968 bytes
#define GEMM_SMEM_MT2 (4 * (2*64*12  + 2*8*136) * 4)   // 59392 bytes

template<int EPI, int MT>
__global__ __launch_bounds__(256, 2) void gemm_tc(
    const __half* __restrict__ A, const uint32_t* __restrict__ Bh,
    const float* __restrict__ bias, void* __restrict__ Cv,
    float* __restrict__ rowsum, int N, int K) {
    constexpr int BM  = MT * 32;
    constexpr int SA  = 2 * BM * 12;     // A area per stage (u32)
    constexpr int SB  = 2 * 8 * 136;     // B area per stage (u32)
    constexpr int STG = SA + SB;
    extern __shared__ uint32_t sm5[];

    const int t    = threadIdx.x;
    const int warp = t >> 5, lane = t & 31;
    const int wm   = warp >> 2, wn = warp & 3;      // 2 x 4 warp grid
    const int g    = lane >> 2, tig = lane & 3;
    const int bm   = blockIdx.y * BM;
    const int bn   = blockIdx.x * 128;

    float acc[MT][4][4];
    #pragma unroll
    for (int i = 0; i < MT; i++)
        #pragma unroll
        for (int j = 0; j < 4; j++)
            #pragma unroll
            for (int r = 0; r < 4; r++) acc[i][j][r] = 0.f;

    const int nkt = K >> 5;

    // A per stage: 2 sub-k-tiles of 16 halves; rows stride 12 u32 (conflict-free reads)
    // B per stage: 2 sub-tiles of [8 kk][136 n] interleaved half2 weights
    #define ISSUE(kt_) do {                                                           \
        int stg_ = (kt_) & 3;                                                         \
        int k0_  = (kt_) << 5;                                                        \
        uint32_t* sa_  = sm5 + stg_ * STG;                                            \
        uint32_t* sbp_ = sa_ + SA;                                                    \
        if (MT == 4) {                                                                \
            int r_ = (t >> 1) & 127; int h_ = t & 1;                                  \
            const __half* gsrc_ = A + (size_t)(bm + r_) * K + k0_ + h_*8;             \
            cp16((uint32_t)__cvta_generic_to_shared(sa_ + r_*12 + h_*4), gsrc_);      \
            cp16((uint32_t)__cvta_generic_to_shared(sa_ + BM*12 + r_*12 + h_*4),      \
                 gsrc_ + 16);                                                         \
        } else {                                                                      \
            int sub_ = t >> 7; int r_ = (t >> 1) & 63; int h_ = t & 1;                \
            cp16((uint32_t)__cvta_generic_to_shared(sa_ + sub_*BM*12 + r_*12 + h_*4), \
                 A + (size_t)(bm + r_) * K + k0_ + sub_*16 + h_*8);                   \
        }                                                                             \
        {                                                                             \
            int kk_ = (t >> 5) & 7; int col_ = (t & 31) << 2;                         \
            const uint32_t* gb_ = Bh + (size_t)((k0_ >> 1) + kk_) * N + bn + col_;    \
            cp16((uint32_t)__cvta_generic_to_shared(sbp_ + kk_*136 + col_), gb_);     \
            cp16((uint32_t)__cvta_generic_to_shared(sbp_ + 8*136 + kk_*136 + col_),   \
                 gb_ + (size_t)8 * N);                                                \
        }                                                                             \
        asm volatile("cp.async.commit_group;\n");                                     \
    } while (0)

    ISSUE(0); ISSUE(1); ISSUE(2);

    for (int kt = 0; kt < nkt; kt++) {
        asm volatile("cp.async.wait_group 2;\n");
        __syncthreads();
        if (kt + 3 < nkt) ISSUE(kt + 3);
        else              asm volatile("cp.async.commit_group;\n");

        const uint32_t* sa  = sm5 + (kt & 3) * STG;
        const uint32_t* sbp = sa + SA;
        #pragma unroll
        for (int sub = 0; sub < 2; sub++) {
            const uint32_t* a_ = sa  + sub * BM * 12;
            const uint32_t* b_ = sbp + sub * 8 * 136;
            uint32_t a[MT][4];
            #pragma unroll
            for (int mt = 0; mt < MT; mt++) {
                int m = wm * (MT * 16) + mt * 16 + g;
                a[mt][0] = a_[m * 12 + tig];
                a[mt][1] = a_[(m + 8) * 12 + tig];
                a[mt][2] = a_[m * 12 + tig + 4];
                a[mt][3] = a_[(m + 8) * 12 + tig + 4];
            }
            #pragma unroll
            for (int nt = 0; nt < 4; nt++) {
                int n = wn * 32 + nt * 8 + g;
                uint32_t b0 = b_[tig * 136 + n];
                uint32_t b1 = b_[(tig + 4) * 136 + n];
                #pragma unroll
                for (int mt = 0; mt < MT; mt++) {
                    asm volatile(
                        "mma.sync.aligned.m16n8k16.row.col.f32.f16.f16.f32 "
                        "{%0,%1,%2,%3}, {%4,%5,%6,%7}, {%8,%9}, {%0,%1,%2,%3};\n"
                        : "+f"(acc[mt][nt][0]), "+f"(acc[mt][nt][1]),
                          "+f"(acc[mt][nt][2]), "+f"(acc[mt][nt][3])
                        : "r"(a[mt][0]), "r"(a[mt][1]), "r"(a[mt][2]), "r"(a[mt][3]),
                          "r"(b0), "r"(b1));
                }
            }
        }
    }
    #undef ISSUE

    // epilogue: c0/c1 at (row g, cols 2tig,2tig+1), c2/c3 at row g+8
    float rs0[MT], rs1[MT];
    if (EPI == 3) {
        #pragma unroll
        for (int mt = 0; mt < MT; mt++) { rs0[mt] = 0.f; rs1[mt] = 0.f; }
    }
    #pragma unroll
    for (int nt = 0; nt < 4; nt++) {
        int n = bn + wn * 32 + nt * 8 + 2 * tig;
        float2 bv = *(const float2*)(bias + n);
        #pragma unroll
        for (int mt = 0; mt < MT; mt++) {
            int r = bm + wm * (MT * 16) + mt * 16 + g;
            float o00 = acc[mt][nt][0] + bv.x, o01 = acc[mt][nt][1] + bv.y;
            float o10 = acc[mt][nt][2] + bv.x, o11 = acc[mt][nt][3] + bv.y;
            if (EPI == 1) {
                o00 = gelu_exact(o00); o01 = gelu_exact(o01);
                o10 = gelu_exact(o10); o11 = gelu_exact(o11);
            }
            if (EPI == 3) {
                o00 = expf(o00); o01 = expf(o01);
                o10 = expf(o10); o11 = expf(o11);
                rs0[mt] += o00 + o01;
                rs1[mt] += o10 + o11;
            }
            if (EPI == 1 || EPI == 2) {
                __half* Ch = (__half*)Cv;
                *(__half2*)(Ch + (size_t)r * N + n)       = __floats2half2_rn(o00, o01);
                *(__half2*)(Ch + (size_t)(r + 8) * N + n) = __floats2half2_rn(o10, o11);
            } else {
                float* Cf = (float*)Cv;
                *(float2*)(Cf + (size_t)r * N + n)       = make_float2(o00, o01);
                *(float2*)(Cf + (size_t)(r + 8) * N + n) = make_float2(o10, o11);
            }
        }
    }
    if (EPI == 3) {
        #pragma unroll
        for (int mt = 0; mt < MT; mt++) {
            float s0 = rs0[mt], s1 = rs1[mt];
            s0 += __shfl_xor_sync(0xffffffffu, s0, 1);
            s0 += __shfl_xor_sync(0xffffffffu, s0, 2);
            s1 += __shfl_xor_sync(0xffffffffu, s1, 1);
            s1 += __shfl_xor_sync(0xffffffffu, s1, 2);
            if (tig == 0) {
                int r = bm + wm * (MT * 16) + mt * 16 + g;
                atomicAdd(&rowsum[r],     s0);
                atomicAdd(&rowsum[r + 8], s1);
            }
        }
    }
}

// =================== tensor-core flash attention (fp16 mma, fp32 softmax/acc) ===================
__global__ __launch_bounds__(128) void attn_kernel(const __half* __restrict__ qkvh,
                                                   __half* __restrict__ out) {
    __shared__ __align__(16) __half   Qs[64][72];
    __shared__ __align__(16) __half   Ks[64][72];
    __shared__ __align__(16) uint32_t Vs2[32][68];

    const int qt = blockIdx.x, h = blockIdx.y, b = blockIdx.z;
    const int t  = threadIdx.x;
    const int w  = t >> 5, lane = t & 31;
    const int g  = lane >> 2, tig = lane & 3;
    const int RS = 3*DIM;
    const __half* base = qkvh + (size_t)(b*SEQ) * RS + h * (3*HD);

    #pragma unroll
    for (int i = 0; i < 4; i++) {
        int f = t + i*128;
        int r = f >> 3, c = (f & 7) << 3;
        *(uint4*)&Qs[r][c] = *(const uint4*)(base + (size_t)(qt*64 + r) * RS + c);
    }
    __syncthreads();

    uint32_t qf[4][4];
    {
        const __half* r0 = &Qs[w*16 + g    ][0];
        const __half* r8 = &Qs[w*16 + g + 8][0];
        #pragma unroll
        for (int kc = 0; kc < 4; kc++) {
            qf[kc][0] = *(const uint32_t*)(r0 + kc*16 + 2*tig);
            qf[kc][1] = *(const uint32_t*)(r8 + kc*16 + 2*tig);
            qf[kc][2] = *(const uint32_t*)(r0 + kc*16 + 8 + 2*tig);
            qf[kc][3] = *(const uint32_t*)(r8 + kc*16 + 8 + 2*tig);
        }
    }

    float m0 = -INFINITY, m1 = -INFINITY, l0 = 0.f, l1 = 0.f;
    float o[8][4];
    #pragma unroll
    for (int i = 0; i < 8; i++)
        #pragma unroll
        for (int j = 0; j < 4; j++) o[i][j] = 0.f;

    const int q0 = qt*64 + w*16 + g;
    const int q1 = q0 + 8;

    for (int kt = 0; kt <= qt; kt++) {
        __syncthreads();
        #pragma unroll
        for (int i = 0; i < 4; i++) {
            int f = t + i*128;
            int r = f >> 3, c = (f & 7) << 3;
            *(uint4*)&Ks[r][c] = *(const uint4*)(base + (size_t)(kt*64 + r) * RS + 64 + c);
        }
        #pragma unroll
        for (int i = 0; i < 2; i++) {
            int f = t + i*128;
            int rp = f >> 3, c = (f & 7) << 3;
            const __half* v0 = base + (size_t)(kt*64 + 2*rp) * RS + 128 + c;
            uint4 lo = *(const uint4*)v0;
            uint4 hi = *(const uint4*)(v0 + RS);
            const ushort* ls = (const ushort*)&lo;
            const ushort* hs = (const ushort*)&hi;
            uint32_t pk[8];
            #pragma unroll
            for (int j = 0; j < 8; j++) pk[j] = (uint32_t)ls[j] | ((uint32_t)hs[j] << 16);
            *(uint4*)&Vs2[rp][c]     = make_uint4(pk[0], pk[1], pk[2], pk[3]);
            *(uint4*)&Vs2[rp][c + 4] = make_uint4(pk[4], pk[5], pk[6], pk[7]);
        }
        __syncthreads();

        float s[8][4];
        #pragma unroll
        for (int i = 0; i < 8; i++)
            #pragma unroll
            for (int j = 0; j < 4; j++) s[i][j] = 0.f;
        #pragma unroll
        for (int kc = 0; kc < 4; kc++) {
            #pragma unroll
            for (int nt = 0; nt < 8; nt++) {
                uint32_t b0 = *(const uint32_t*)(&Ks[nt*8 + g][kc*16 + 2*tig]);
                uint32_t b1 = *(const uint32_t*)(&Ks[nt*8 + g][kc*16 + 8 + 2*tig]);
                asm volatile(
                    "mma.sync.aligned.m16n8k16.row.col.f32.f16.f16.f32 "
                    "{%0,%1,%2,%3}, {%4,%5,%6,%7}, {%8,%9}, {%0,%1,%2,%3};\n"
                    : "+f"(s[nt][0]), "+f"(s[nt][1]), "+f"(s[nt][2]), "+f"(s[nt][3])
                    : "r"(qf[kc][0]), "r"(qf[kc][1]), "r"(qf[kc][2]), "r"(qf[kc][3]),
                      "r"(b0), "r"(b1));
            }
        }

        float tm0 = -INFINITY, tm1 = -INFINITY;
        #pragma unroll
        for (int nt = 0; nt < 8; nt++) {
            int c0 = kt*64 + nt*8 + 2*tig, c1 = c0 + 1;
            s[nt][0] = (c0 <= q0) ? s[nt][0] * 0.125f : -INFINITY;
            s[nt][1] = (c1 <= q0) ? s[nt][1] * 0.125f : -INFINITY;
            s[nt][2] = (c0 <= q1) ? s[nt][2] * 0.125f : -INFINITY;
            s[nt][3] = (c1 <= q1) ? s[nt][3] * 0.125f : -INFINITY;
            tm0 = fmaxf(tm0, fmaxf(s[nt][0], s[nt][1]));
            tm1 = fmaxf(tm1, fmaxf(s[nt][2], s[nt][3]));
        }
        tm0 = fmaxf(tm0, __shfl_xor_sync(0xffffffffu, tm0, 1));
        tm0 = fmaxf(tm0, __shfl_xor_sync(0xffffffffu, tm0, 2));
        tm1 = fmaxf(tm1, __shfl_xor_sync(0xffffffffu, tm1, 1));
        tm1 = fmaxf(tm1, __shfl_xor_sync(0xffffffffu, tm1, 2));

        float nm0 = fmaxf(m0, tm0), nm1 = fmaxf(m1, tm1);
        float corr0 = expf(m0 - nm0), corr1 = expf(m1 - nm1);
        m0 = nm0; m1 = nm1;

        uint32_t pf[4][4];
        float ls0 = 0.f, ls1 = 0.f;
        #pragma unroll
        for (int j = 0; j < 4; j++) {
            float p00 = expf(s[2*j][0]   - m0), p01 = expf(s[2*j][1]   - m0);
            float p02 = expf(s[2*j][2]   - m1), p03 = expf(s[2*j][3]   - m1);
            float p10 = expf(s[2*j+1][0] - m0), p11 = expf(s[2*j+1][1] - m0);
            float p12 = expf(s[2*j+1][2] - m1), p13 = expf(s[2*j+1][3] - m1);
            ls0 += p00 + p01 + p10 + p11;
            ls1 += p02 + p03 + p12 + p13;
            pf[j][0] = packh2(p00, p01);
            pf[j][1] = packh2(p02, p03);
            pf[j][2] = packh2(p10, p11);
            pf[j][3] = packh2(p12, p13);
        }
        ls0 += __shfl_xor_sync(0xffffffffu, ls0, 1);
        ls0 += __shfl_xor_sync(0xffffffffu, ls0, 2);
        ls1 += __shfl_xor_sync(0xffffffffu, ls1, 1);
        ls1 += __shfl_xor_sync(0xffffffffu, ls1, 2);
        l0 = l0 * corr0 + ls0;
        l1 = l1 * corr1 + ls1;

        #pragma unroll
        for (int nt = 0; nt < 8; nt++) {
            o[nt][0] *= corr0; o[nt][1] *= corr0;
            o[nt][2] *= corr1; o[nt][3] *= corr1;
        }

        #pragma unroll
        for (int j = 0; j < 4; j++) {
            #pragma unroll
            for (int nt = 0; nt < 8; nt++) {
                uint32_t b0 = Vs2[8*j + tig    ][nt*8 + g];
                uint32_t b1 = Vs2[8*j + tig + 4][nt*8 + g];
                asm volatile(
                    "mma.sync.aligned.m16n8k16.row.col.f32.f16.f16.f32 "
                    "{%0,%1,%2,%3}, {%4,%5,%6,%7}, {%8,%9}, {%0,%1,%2,%3};\n"
                    : "+f"(o[nt][0]), "+f"(o[nt][1]), "+f"(o[nt][2]), "+f"(o[nt][3])
                    : "r"(pf[j][0]), "r"(pf[j][1]), "r"(pf[j][2]), "r"(pf[j][3]),
                      "r"(b0), "r"(b1));
            }
        }
    }

    float inv0 = 1.f / l0, inv1 = 1.f / l1;
    __half* or0 = out + (size_t)(b*SEQ + q0) * DIM + h * HD;
    __half* or1 = out + (size_t)(b*SEQ + q1) * DIM + h * HD;
    #pragma unroll
    for (int nt = 0; nt < 8; nt++) {
        int c = nt*8 + 2*tig;
        *(__half2*)(or0 + c) = __floats2half2_rn(o[nt][0] * inv0, o[nt][1] * inv0);
        *(__half2*)(or1 + c) = __floats2half2_rn(o[nt][2] * inv1, o[nt][3] * inv1);
    }
}

// =================== residual add + LayerNorm (fp32 + fp16 out) ===================
__global__ __launch_bounds__(256) void add_ln_kernel(
    const float* __restrict__ x, const float* __restrict__ a,
    const float* __restrict__ scale, const float* __restrict__ bias,
    float* __restrict__ out, __half* __restrict__ outh, int has_a) {
    int row = blockIdx.x;
    const float* xr = x + (size_t)row * DIM;
    const float* ar = a + (size_t)row * DIM;
    int t = threadIdx.x;
    float v[4];
    float s = 0.f, s2 = 0.f;
    #pragma unroll
    for (int i = 0; i < 4; i++) {
        int d = t + i*256;
        float val = xr[d] + (has_a ? ar[d] : 0.f);
        v[i] = val; s += val; s2 += val*val;
    }
    __shared__ float red[2][8];
    #pragma unroll
    for (int off = 16; off; off >>= 1) {
        s  += __shfl_xor_sync(0xffffffffu, s,  off);
        s2 += __shfl_xor_sync(0xffffffffu, s2, off);
    }
    if ((t & 31) == 0) { red[0][t>>5] = s; red[1][t>>5] = s2; }
    __syncthreads();
    float ts = 0.f, ts2 = 0.f;
    #pragma unroll
    for (int i = 0; i < 8; i++) { ts += red[0][i]; ts2 += red[1][i]; }
    float mean = ts * (1.0f/DIM);
    float var  = ts2 * (1.0f/DIM) - mean*mean;
    float inv  = rsqrtf(var + 1e-5f);
    float*  orow  = out  + (size_t)row * DIM;
    __half* orowh = outh + (size_t)row * DIM;
    #pragma unroll
    for (int i = 0; i < 4; i++) {
        int d = t + i*256;
        float val = (v[i] - mean) * inv * scale[d] + bias[d];
        orow[d]  = val;
        orowh[d] = __float2half(val);
    }
}

// =================== fused-softmax helpers ===================
__global__ void zero_rowsum_kernel(float* __restrict__ rowsum) {
    rowsum[blockIdx.x * 256 + threadIdx.x] = 0.f;
}
__global__ __launch_bounds__(256) void normalize_kernel(float* __restrict__ out,
                                                        const float* __restrict__ rowsum) {
    int row = blockIdx.x;
    float inv = 1.f / rowsum[row];
    float4* r = (float4*)(out + (size_t)row * VOCAB);
    for (int i = threadIdx.x; i < VOCAB/4; i += 256) {
        float4 v = r[i];
        v.x *= inv; v.y *= inv; v.z *= inv; v.w *= inv;
        r[i] = v;
    }
}

// =================== launch ===================
extern "C" void kernel_launch(void* const* d_in, const int* in_sizes, int n_in,
                              void* d_out, int out_size) {
    const int*   X      = (const int*)  d_in[0];
    const float* tok    = (const float*)d_in[1];
    const float* pos    = (const float*)d_in[2];
    const float* qkv_w  = (const float*)d_in[3];
    const float* qkv_b  = (const float*)d_in[4];
    const float* out_w  = (const float*)d_in[5];
    const float* out_b  = (const float*)d_in[6];
    const float* ln1_s  = (const float*)d_in[7];
    const float* ln1_b  = (const float*)d_in[8];
    const float* ln2_s  = (const float*)d_in[9];
    const float* ln2_b  = (const float*)d_in[10];
    const float* ff1_w  = (const float*)d_in[11];
    const float* ff1_b  = (const float*)d_in[12];
    const float* ff2_w  = (const float*)d_in[13];
    const float* ff2_b  = (const float*)d_in[14];
    const float* lnf_s  = (const float*)d_in[15];
    const float* lnf_b  = (const float*)d_in[16];
    const float* head_w = (const float*)d_in[17];
    const float* head_b = (const float*)d_in[18];
    float* outp = (float*)d_out;

    float *x, *tmp, *rowsum;
    __half *xh, *qkvh, *aoh, *ffh;
    uint32_t *qkvwh, *outwh, *ff1wh, *ff2wh, *headwh;
    cudaGetSymbolAddress((void**)&x,      g_x);
    cudaGetSymbolAddress((void**)&xh,     g_xh);
    cudaGetSymbolAddress((void**)&qkvh,   g_qkvh);
    cudaGetSymbolAddress((void**)&aoh,    g_aoh);
    cudaGetSymbolAddress((void**)&ffh,    g_ffh);
    cudaGetSymbolAddress((void**)&tmp,    g_t);
    cudaGetSymbolAddress((void**)&rowsum, g_rowsum);
    cudaGetSymbolAddress((void**)&qkvwh,  g_qkvwh);
    cudaGetSymbolAddress((void**)&outwh,  g_outwh);
    cudaGetSymbolAddress((void**)&ff1wh,  g_ff1wh);
    cudaGetSymbolAddress((void**)&ff2wh,  g_ff2wh);
    cudaGetSymbolAddress((void**)&headwh, g_headwh);

    cudaFuncSetAttribute(gemm_tc<2,4>, cudaFuncAttributeMaxDynamicSharedMemorySize, GEMM_SMEM_MT4);
    cudaFuncSetAttribute(gemm_tc<1,4>, cudaFuncAttributeMaxDynamicSharedMemorySize, GEMM_SMEM_MT4);
    cudaFuncSetAttribute(gemm_tc<3,4>, cudaFuncAttributeMaxDynamicSharedMemorySize, GEMM_SMEM_MT4);
    cudaFuncSetAttribute(gemm_tc<0,2>, cudaFuncAttributeMaxDynamicSharedMemorySize, GEMM_SMEM_MT2);

    // one-time weight conversions (per launch)
    convert_w<<<(DIM/2)*3*DIM/256, 256>>>(qkv_w,  qkvwh,  3*DIM);
    convert_w<<<(DIM/2)*DIM/256,   256>>>(out_w,  outwh,  DIM);
    convert_w<<<(DIM/2)*FFD/256,   256>>>(ff1_w,  ff1wh,  FFD);
    convert_w<<<(FFD/2)*DIM/256,   256>>>(ff2_w,  ff2wh,  DIM);
    convert_w<<<(DIM/2)*VOCAB/256, 256>>>(head_w, headwh, VOCAB);

    embed_kernel<<<ROWS, 256>>>(X, tok, pos, x, xh);

    for (int l = 0; l < LAYERS; l++) {
        gemm_tc<2,4><<<dim3(3*DIM/128, ROWS/128), 256, GEMM_SMEM_MT4>>>(xh, qkvwh, qkv_b, qkvh, nullptr, 3*DIM, DIM);
        attn_kernel<<<dim3(SEQ/64, NH, BATCH), 128>>>(qkvh, aoh);
        gemm_tc<0,2><<<dim3(DIM/128, ROWS/64), 256, GEMM_SMEM_MT2>>>(aoh, outwh, out_b, tmp, nullptr, DIM, DIM);
        add_ln_kernel<<<ROWS, 256>>>(x, tmp, ln1_s, ln1_b, x, xh, 1);
        gemm_tc<1,4><<<dim3(FFD/128, ROWS/128), 256, GEMM_SMEM_MT4>>>(xh, ff1wh, ff1_b, ffh, nullptr, FFD, DIM);
        gemm_tc<0,2><<<dim3(DIM/128, ROWS/64), 256, GEMM_SMEM_MT2>>>(ffh, ff2wh, ff2_b, tmp, nullptr, DIM, FFD);
        add_ln_kernel<<<ROWS, 256>>>(x, tmp, ln2_s, ln2_b, x, xh, 1);
    }
    add_ln_kernel<<<ROWS, 256>>>(x, x, lnf_s, lnf_b, x, xh, 0);
    zero_rowsum_kernel<<<ROWS/256, 256>>>(rowsum);
    gemm_tc<3,4><<<dim3(VOCAB/128, ROWS/128), 256, GEMM_SMEM_MT4>>>(xh, headwh, head_b, outp, rowsum, VOCAB, DIM);
    normalize_kernel<<<ROWS, 256>>>(outp, rowsum);
}